// round 1
// baseline (speedup 1.0000x reference)
#include <cuda_runtime.h>
#include <math.h>

// Problem constants
#define B_ 32
#define S_ 64
#define T_ 64
#define H_ 512
#define H3_ 1536
#define V_ 32000
#define NVT 500          // V_/64 vocab tiles
#define ROWS 2048        // B_*S_ == B_*T_

// -------------------- scratch (device globals; no allocation) --------------------
__device__ float g_esrc[ROWS * H_];       // [B,S,E]
__device__ float g_gx_f[ROWS * H3_];      // precomputed input gates fwd
__device__ float g_gx_b[ROWS * H3_];      // precomputed input gates bwd
__device__ float g_srchid[ROWS * 1024];   // [B,S,2H] encoder outputs
__device__ float g_Uh[ROWS * H_];         // [B,S,Ht]
__device__ float g_hf[B_ * H_];
__device__ float g_hb[B_ * H_];
__device__ float g_hd[B_ * H_];
__device__ float g_ghf[B_ * H3_];
__device__ float g_ghb[B_ * H3_];
__device__ float g_a[B_ * H_];
__device__ float g_e[B_ * S_];
__device__ float g_x[B_ * H3_];           // [emb(512) | context(1024)]
__device__ float g_gxd[B_ * H3_];
__device__ float g_ghd[B_ * H3_];
__device__ float g_decout[ROWS * H_];
__device__ float g_partial[ROWS * NVT];   // per-row per-vocab-tile sum(exp(logit))
__device__ float g_picked[ROWS];
__device__ float g_rowloss[ROWS];
__device__ float g_rowvalid[ROWS];

__device__ __forceinline__ float sigf(float x) { return 1.f / (1.f + __expf(-x)); }

// -------------------- init / embed --------------------
__global__ void init_states() {
    int i = blockIdx.x * 256 + threadIdx.x;
    if (i < B_ * H_) { g_hf[i] = 0.f; g_hb[i] = 0.f; g_hd[i] = 0.f; }
}

__global__ void embed_src(const int* __restrict__ src_seqs,
                          const float* __restrict__ src_emb) {
    int i = blockIdx.x * 256 + threadIdx.x;      // < 2048*512
    int bs = i >> 9, j = i & 511;
    int tok = src_seqs[bs];
    g_esrc[i] = src_emb[tok * H_ + j];
}

// -------------------- generic tiled SGEMM: C[M,N] = A[M,K] * B[N,K]^T + bias --------------------
// Two independent problems selected by blockIdx.z (same M,N; K may differ).
template<int BM, int BN, int BK, int TM, int TN>
__global__ void gemm_dual(const float* __restrict__ A0, const float* __restrict__ B0,
                          const float* __restrict__ bias0, float* __restrict__ C0, int K0,
                          const float* __restrict__ A1, const float* __restrict__ B1,
                          const float* __restrict__ bias1, float* __restrict__ C1, int K1,
                          int M, int N) {
    constexpr int NTHREADS = (BM / TM) * (BN / TN);
    __shared__ float As[BK][BM];
    __shared__ float Bs[BK][BN];

    const float* A; const float* Bw; const float* bias; float* C; int K;
    if (blockIdx.z == 0) { A = A0; Bw = B0; bias = bias0; C = C0; K = K0; }
    else                 { A = A1; Bw = B1; bias = bias1; C = C1; K = K1; }

    int tid = threadIdx.x;
    int tx = tid % (BN / TN);
    int ty = tid / (BN / TN);
    int row0 = blockIdx.y * BM;
    int col0 = blockIdx.x * BN;

    float acc[TM][TN];
#pragma unroll
    for (int i = 0; i < TM; i++)
#pragma unroll
        for (int j = 0; j < TN; j++) acc[i][j] = 0.f;

    for (int k0 = 0; k0 < K; k0 += BK) {
        for (int i = tid; i < BM * BK; i += NTHREADS) {
            int m = i / BK, kk = i % BK;
            As[kk][m] = A[(row0 + m) * K + k0 + kk];
        }
        for (int i = tid; i < BN * BK; i += NTHREADS) {
            int n = i / BK, kk = i % BK;
            Bs[kk][n] = Bw[(col0 + n) * K + k0 + kk];
        }
        __syncthreads();
#pragma unroll
        for (int kk = 0; kk < BK; kk++) {
            float ra[TM], rb[TN];
#pragma unroll
            for (int i = 0; i < TM; i++) ra[i] = As[kk][ty * TM + i];
#pragma unroll
            for (int j = 0; j < TN; j++) rb[j] = Bs[kk][tx * TN + j];
#pragma unroll
            for (int i = 0; i < TM; i++)
#pragma unroll
                for (int j = 0; j < TN; j++) acc[i][j] += ra[i] * rb[j];
        }
        __syncthreads();
    }
#pragma unroll
    for (int i = 0; i < TM; i++)
#pragma unroll
        for (int j = 0; j < TN; j++) {
            int r = row0 + ty * TM + i;
            int c = col0 + tx * TN + j;
            C[r * N + c] = acc[i][j] + bias[c];
        }
}

// -------------------- encoder step pointwise (both directions) --------------------
__global__ void enc_pointwise(const int* __restrict__ slen, int t) {
    int idx = blockIdx.x * 256 + threadIdx.x;   // < 32*512
    int dir = blockIdx.y;
    int b = idx >> 9, j = idx & 511;
    int tf = dir ? (S_ - 1 - t) : t;
    const float* gx = (dir ? g_gx_b : g_gx_f) + (b * S_ + tf) * H3_;
    const float* gh = (dir ? g_ghb : g_ghf) + b * H3_;
    float* hst = dir ? g_hb : g_hf;
    float h = hst[idx];
    float r = sigf(gx[j] + gh[j]);
    float z = sigf(gx[H_ + j] + gh[H_ + j]);
    float n = tanhf(gx[2 * H_ + j] + r * gh[2 * H_ + j]);
    float hn = (1.f - z) * n + z * h;
    bool m = tf < slen[b];
    hst[idx] = m ? hn : h;
    g_srchid[(b * S_ + tf) * 1024 + dir * H_ + j] = m ? hn : 0.f;
}

// -------------------- attention energies --------------------
__global__ void energy_kernel(const float* __restrict__ Av,
                              const int* __restrict__ slen) {
    int s = blockIdx.x, b = blockIdx.y;
    const float* u = g_Uh + (b * S_ + s) * H_;
    const float* ab = g_a + b * H_;
    float p = 0.f;
    for (int j = threadIdx.x; j < H_; j += 128)
        p += Av[j] * tanhf(u[j] + ab[j]);
#pragma unroll
    for (int o = 16; o > 0; o >>= 1) p += __shfl_xor_sync(0xffffffffu, p, o);
    __shared__ float w[4];
    if ((threadIdx.x & 31) == 0) w[threadIdx.x >> 5] = p;
    __syncthreads();
    if (threadIdx.x == 0) {
        float e = w[0] + w[1] + w[2] + w[3];
        if (s >= slen[b]) e += -1e9f;
        g_e[b * S_ + s] = e;
    }
}

// -------------------- softmax + context + build x --------------------
__global__ void softmax_ctx(const int* __restrict__ tgt_seqs,
                            const float* __restrict__ tgt_emb, int t) {
    int b = blockIdx.x;
    int tid = threadIdx.x;
    __shared__ float se[S_];
    if (tid < S_) se[tid] = g_e[b * S_ + tid];
    __syncthreads();
    float m = -1e30f;
    for (int i = 0; i < S_; i++) m = fmaxf(m, se[i]);
    __syncthreads();
    if (tid < S_) se[tid] = __expf(se[tid] - m);
    __syncthreads();
    float sum = 0.f;
    for (int i = 0; i < S_; i++) sum += se[i];
    float inv = 1.f / sum;

    for (int j = tid; j < 1024; j += 256) {
        float c = 0.f;
        for (int s = 0; s < S_; s++) c += se[s] * g_srchid[(b * S_ + s) * 1024 + j];
        g_x[b * H3_ + H_ + j] = c * inv;
    }
    int tok = tgt_seqs[b * T_ + t];
    for (int j = tid; j < H_; j += 256)
        g_x[b * H3_ + j] = tgt_emb[tok * H_ + j];
}

// -------------------- decoder step pointwise --------------------
__global__ void dec_pointwise(const int* __restrict__ tlen, int t) {
    int idx = blockIdx.x * 256 + threadIdx.x;   // < 32*512
    int b = idx >> 9, j = idx & 511;
    const float* gx = g_gxd + b * H3_;
    const float* gh = g_ghd + b * H3_;
    float h = g_hd[idx];
    float r = sigf(gx[j] + gh[j]);
    float z = sigf(gx[H_ + j] + gh[H_ + j]);
    float n = tanhf(gx[2 * H_ + j] + r * gh[2 * H_ + j]);
    float hn = (1.f - z) * n + z * h;
    bool m = t < tlen[b];
    g_hd[idx] = m ? hn : h;
    g_decout[(b * T_ + t) * H_ + j] = m ? hn : 0.f;
}

// -------------------- fused logits GEMM + per-tile exp-sum + pick --------------------
__global__ void logits_lse(const float* __restrict__ W,
                           const float* __restrict__ bias,
                           const int* __restrict__ tseq) {
    constexpr int BM = 64, BN = 64, BK = 16;
    __shared__ float As[BK][BM];
    __shared__ float Bs[BK][BN];
    __shared__ float red[64][17];
    int tid = threadIdx.x;
    int tx = tid & 15, ty = tid >> 4;
    int row0 = blockIdx.y * BM;
    int col0 = blockIdx.x * BN;

    float acc[4][4];
#pragma unroll
    for (int i = 0; i < 4; i++)
#pragma unroll
        for (int j = 0; j < 4; j++) acc[i][j] = 0.f;

    for (int k0 = 0; k0 < H_; k0 += BK) {
        for (int i = tid; i < BM * BK; i += 256) {
            int m = i >> 4, kk = i & 15;
            As[kk][m] = g_decout[(row0 + m) * H_ + k0 + kk];
        }
        for (int i = tid; i < BN * BK; i += 256) {
            int n = i >> 4, kk = i & 15;
            Bs[kk][n] = W[(col0 + n) * H_ + k0 + kk];
        }
        __syncthreads();
#pragma unroll
        for (int kk = 0; kk < BK; kk++) {
            float ra[4], rb[4];
#pragma unroll
            for (int i = 0; i < 4; i++) ra[i] = As[kk][ty * 4 + i];
#pragma unroll
            for (int j = 0; j < 4; j++) rb[j] = Bs[kk][tx * 4 + j];
#pragma unroll
            for (int i = 0; i < 4; i++)
#pragma unroll
                for (int j = 0; j < 4; j++) acc[i][j] += ra[i] * rb[j];
        }
        __syncthreads();
    }

#pragma unroll
    for (int i = 0; i < 4; i++) {
        int row = row0 + ty * 4 + i;
        int bb = row >> 6, tt = row & 63;
        int g = (tt < T_ - 1) ? tseq[bb * T_ + tt + 1] : 0;
        float pse = 0.f;
#pragma unroll
        for (int j = 0; j < 4; j++) {
            int col = col0 + tx * 4 + j;
            float v = acc[i][j] + bias[col];
            pse += __expf(v);           // logits provably small: unshifted exp safe
            if (col == g) g_picked[row] = v;
        }
        red[ty * 4 + i][tx] = pse;
    }
    __syncthreads();
    if (tid < 64) {
        float s = 0.f;
#pragma unroll
        for (int x = 0; x < 16; x++) s += red[tid][x];
        g_partial[(row0 + tid) * NVT + blockIdx.x] = s;
    }
}

// -------------------- per-row lse + nll --------------------
__global__ void rowloss_kernel(const int* __restrict__ tseq) {
    int r = blockIdx.x, tid = threadIdx.x;
    float s = 0.f;
    for (int v = tid; v < NVT; v += 128) s += g_partial[r * NVT + v];
#pragma unroll
    for (int o = 16; o > 0; o >>= 1) s += __shfl_xor_sync(0xffffffffu, s, o);
    __shared__ float w[4];
    if ((tid & 31) == 0) w[tid >> 5] = s;
    __syncthreads();
    if (tid == 0) {
        float sum = w[0] + w[1] + w[2] + w[3];
        int b = r >> 6, t = r & 63;
        int g = (t < T_ - 1) ? tseq[b * T_ + t + 1] : 0;
        if (g != 0) { g_rowloss[r] = logf(sum) - g_picked[r]; g_rowvalid[r] = 1.f; }
        else        { g_rowloss[r] = 0.f;                     g_rowvalid[r] = 0.f; }
    }
}

__global__ void final_kernel(float* __restrict__ out) {
    int tid = threadIdx.x;
    float s = 0.f, c = 0.f;
    for (int r = tid; r < ROWS; r += 256) { s += g_rowloss[r]; c += g_rowvalid[r]; }
#pragma unroll
    for (int o = 16; o > 0; o >>= 1) {
        s += __shfl_xor_sync(0xffffffffu, s, o);
        c += __shfl_xor_sync(0xffffffffu, c, o);
    }
    __shared__ float ws[8], wc[8];
    if ((tid & 31) == 0) { ws[tid >> 5] = s; wc[tid >> 5] = c; }
    __syncthreads();
    if (tid == 0) {
        float S = 0.f, C = 0.f;
        for (int i = 0; i < 8; i++) { S += ws[i]; C += wc[i]; }
        out[0] = S / C;
    }
}

// -------------------- launch --------------------
extern "C" void kernel_launch(void* const* d_in, const int* in_sizes, int n_in,
                              void* d_out, int out_size) {
    const int*   src_seqs = (const int*)d_in[0];
    const int*   src_len  = (const int*)d_in[1];
    const int*   tgt_seqs = (const int*)d_in[2];
    const int*   tgt_len  = (const int*)d_in[3];
    const float* src_emb  = (const float*)d_in[4];
    const float* eWih_f   = (const float*)d_in[5];
    const float* eWhh_f   = (const float*)d_in[6];
    const float* ebih_f   = (const float*)d_in[7];
    const float* ebhh_f   = (const float*)d_in[8];
    const float* eWih_b   = (const float*)d_in[9];
    const float* eWhh_b   = (const float*)d_in[10];
    const float* ebih_b   = (const float*)d_in[11];
    const float* ebhh_b   = (const float*)d_in[12];
    const float* tgt_emb  = (const float*)d_in[13];
    const float* dWih     = (const float*)d_in[14];
    const float* dWhh     = (const float*)d_in[15];
    const float* dbih     = (const float*)d_in[16];
    const float* dbhh     = (const float*)d_in[17];
    const float* U_w      = (const float*)d_in[18];
    const float* U_b      = (const float*)d_in[19];
    const float* A_W      = (const float*)d_in[20];
    const float* A_b      = (const float*)d_in[21];
    const float* A_v      = (const float*)d_in[22];
    const float* out_w    = (const float*)d_in[23];
    const float* out_b    = (const float*)d_in[24];

    // device addresses of scratch (queried every call; no caching, no allocation)
    float *esrc, *gxf, *gxb, *srchid, *uh, *hf, *hb, *hd, *ghf, *ghb, *a_, *x_, *gxd, *ghd;
    cudaGetSymbolAddress((void**)&esrc, g_esrc);
    cudaGetSymbolAddress((void**)&gxf, g_gx_f);
    cudaGetSymbolAddress((void**)&gxb, g_gx_b);
    cudaGetSymbolAddress((void**)&srchid, g_srchid);
    cudaGetSymbolAddress((void**)&uh, g_Uh);
    cudaGetSymbolAddress((void**)&hf, g_hf);
    cudaGetSymbolAddress((void**)&hb, g_hb);
    cudaGetSymbolAddress((void**)&hd, g_hd);
    cudaGetSymbolAddress((void**)&ghf, g_ghf);
    cudaGetSymbolAddress((void**)&ghb, g_ghb);
    cudaGetSymbolAddress((void**)&a_, g_a);
    cudaGetSymbolAddress((void**)&x_, g_x);
    cudaGetSymbolAddress((void**)&gxd, g_gxd);
    cudaGetSymbolAddress((void**)&ghd, g_ghd);

    init_states<<<64, 256>>>();
    embed_src<<<4096, 256>>>(src_seqs, src_emb);

    // gx for both encoder directions: [2048,1536] = e_src[2048,512] @ Wih^T
    gemm_dual<64, 64, 16, 4, 4><<<dim3(24, 32, 2), 256>>>(
        esrc, eWih_f, ebih_f, gxf, H_,
        esrc, eWih_b, ebih_b, gxb, H_, ROWS, H3_);

    // encoder recurrence
    for (int t = 0; t < S_; t++) {
        gemm_dual<32, 32, 16, 2, 2><<<dim3(48, 1, 2), 256>>>(
            hf, eWhh_f, ebhh_f, ghf, H_,
            hb, eWhh_b, ebhh_b, ghb, H_, B_, H3_);
        enc_pointwise<<<dim3(64, 2), 256>>>(src_len, t);
    }

    // Uh = src_hidden @ U_w^T + U_b : [2048,512], K=1024
    gemm_dual<64, 64, 16, 4, 4><<<dim3(8, 32, 1), 256>>>(
        srchid, U_w, U_b, uh, 1024,
        srchid, U_w, U_b, uh, 1024, ROWS, H_);

    // decoder recurrence
    for (int t = 0; t < T_; t++) {
        gemm_dual<32, 32, 16, 2, 2><<<dim3(16, 1, 1), 256>>>(
            hd, A_W, A_b, a_, H_,
            hd, A_W, A_b, a_, H_, B_, H_);
        energy_kernel<<<dim3(S_, B_), 128>>>(A_v, src_len);
        softmax_ctx<<<B_, 256>>>(tgt_seqs, tgt_emb, t);
        gemm_dual<32, 32, 16, 2, 2><<<dim3(48, 1, 2), 256>>>(
            x_, dWih, dbih, gxd, H3_,
            hd, dWhh, dbhh, ghd, H_, B_, H3_);
        dec_pointwise<<<64, 256>>>(tgt_len, t);
    }

    // fused output projection + exp-sums + picked logits
    logits_lse<<<dim3(NVT, 32), 256>>>(out_w, out_b, tgt_seqs);
    rowloss_kernel<<<ROWS, 128>>>(tgt_seqs);
    final_kernel<<<1, 256>>>((float*)d_out);
}

// round 2
// speedup vs baseline: 2.6850x; 2.6850x over previous
#include <cuda_runtime.h>
#include <cuda_bf16.h>
#include <math.h>
#include <stdint.h>

// Problem constants
#define B_ 32
#define S_ 64
#define T_ 64
#define H_ 512
#define H3_ 1536
#define V_ 32000
#define NVT 250          // V_/128 vocab tiles
#define ROWS 2048        // B_*S_ == B_*T_

// -------------------- scratch (device globals; no allocation) --------------------
__device__ float g_esrc[ROWS * H_];
__device__ float g_gx_f[ROWS * H3_];
__device__ float g_gx_b[ROWS * H3_];
__device__ float g_srchid[ROWS * 1024];
__device__ float g_Uh[ROWS * H_];
__device__ float g_hf[B_ * H_];
__device__ float g_hb[B_ * H_];
__device__ float g_hd[B_ * H_];
__device__ float g_epart[4 * B_ * H3_];    // [dir*2+ksplit][32][1536]
__device__ float g_apart[2 * B_ * H_];     // [ksplit][32][512]
__device__ float g_dpart[4 * B_ * H3_];    // [chunk][32][1536] (0..2 gxd, 3 ghd)
__device__ float g_x[B_ * H3_];            // [emb(512) | context(1024)]
__device__ float g_decout[ROWS * H_];
__device__ __nv_bfloat16 g_decbf[ROWS * H_];
__device__ __nv_bfloat16 g_Wbf[V_ * H_];
__device__ float g_partial[ROWS * NVT];
__device__ float g_picked[ROWS];
__device__ float g_rowloss[ROWS];
__device__ float g_rowvalid[ROWS];

__device__ __forceinline__ float sigf(float x) { return 1.f / (1.f + __expf(-x)); }

// -------------------- init / embed --------------------
__global__ void init_states() {
    int i = blockIdx.x * 256 + threadIdx.x;
    if (i < B_ * H_) { g_hf[i] = 0.f; g_hb[i] = 0.f; g_hd[i] = 0.f; }
}

__global__ void embed_src(const int* __restrict__ src_seqs,
                          const float* __restrict__ src_emb) {
    int i = blockIdx.x * 256 + threadIdx.x;
    int bs = i >> 9, j = i & 511;
    int tok = src_seqs[bs];
    g_esrc[i] = src_emb[tok * H_ + j];
}

// -------------------- big fp32 GEMM (gx precompute, Uh) --------------------
template<int BM, int BN, int BK, int TM, int TN>
__global__ void gemm_dual(const float* __restrict__ A0, const float* __restrict__ B0,
                          const float* __restrict__ bias0, float* __restrict__ C0, int K0,
                          const float* __restrict__ A1, const float* __restrict__ B1,
                          const float* __restrict__ bias1, float* __restrict__ C1, int K1,
                          int M, int N) {
    constexpr int NTHREADS = (BM / TM) * (BN / TN);
    __shared__ float As[BK][BM];
    __shared__ float Bs[BK][BN];
    const float* A; const float* Bw; const float* bias; float* C; int K;
    if (blockIdx.z == 0) { A = A0; Bw = B0; bias = bias0; C = C0; K = K0; }
    else                 { A = A1; Bw = B1; bias = bias1; C = C1; K = K1; }
    int tid = threadIdx.x;
    int tx = tid % (BN / TN);
    int ty = tid / (BN / TN);
    int row0 = blockIdx.y * BM;
    int col0 = blockIdx.x * BN;
    float acc[TM][TN];
#pragma unroll
    for (int i = 0; i < TM; i++)
#pragma unroll
        for (int j = 0; j < TN; j++) acc[i][j] = 0.f;
    for (int k0 = 0; k0 < K; k0 += BK) {
        for (int i = tid; i < BM * BK; i += NTHREADS) {
            int m = i / BK, kk = i % BK;
            As[kk][m] = A[(row0 + m) * K + k0 + kk];
        }
        for (int i = tid; i < BN * BK; i += NTHREADS) {
            int n = i / BK, kk = i % BK;
            Bs[kk][n] = Bw[(col0 + n) * K + k0 + kk];
        }
        __syncthreads();
#pragma unroll
        for (int kk = 0; kk < BK; kk++) {
            float ra[TM], rb[TN];
#pragma unroll
            for (int i = 0; i < TM; i++) ra[i] = As[kk][ty * TM + i];
#pragma unroll
            for (int j = 0; j < TN; j++) rb[j] = Bs[kk][tx * TN + j];
#pragma unroll
            for (int i = 0; i < TM; i++)
#pragma unroll
                for (int j = 0; j < TN; j++) acc[i][j] += ra[i] * rb[j];
        }
        __syncthreads();
    }
#pragma unroll
    for (int i = 0; i < TM; i++)
#pragma unroll
        for (int j = 0; j < TN; j++) {
            int r = row0 + ty * TM + i;
            int c = col0 + tx * TN + j;
            C[r * N + c] = acc[i][j] + bias[c];
        }
}

// -------------------- small M=32 GEMM tile: C[32, n0:n0+64] = A[32,KT*16] @ W^T --------------------
// A: row stride lda (already offset to k-start). W: row stride ldw (already offset to k-start).
// C overwritten (partial slot), row stride ldc.
template<int KTILES>
__device__ __forceinline__ void gemm32_tile(const float* __restrict__ A, int lda,
                                            const float* __restrict__ W, int ldw,
                                            float* __restrict__ C, int ldc, int n0) {
    __shared__ float As[16][34];
    __shared__ float Bs[16][68];
    int tid = threadIdx.x;
    int tx = tid & 15;          // n/4
    int ty = tid >> 4;          // m/2
    float acc[2][4];
#pragma unroll
    for (int i = 0; i < 2; i++)
#pragma unroll
        for (int j = 0; j < 4; j++) acc[i][j] = 0.f;

    for (int kt = 0; kt < KTILES; kt++) {
        int kb = kt * 16;
        {   // As: 32x16, 2 elems/thread
            int k = tid & 15, m = tid >> 4;          // m 0..15
            As[k][m] = A[m * lda + kb + k];
            As[k][m + 16] = A[(m + 16) * lda + kb + k];
        }
        {   // Bs: 64x16, 4 elems/thread
#pragma unroll
            for (int r = 0; r < 4; r++) {
                int i = tid + r * 256;
                int k = i & 15, n = i >> 4;
                Bs[k][n] = W[(n0 + n) * ldw + kb + k];
            }
        }
        __syncthreads();
#pragma unroll
        for (int k = 0; k < 16; k++) {
            float2 ra = *(const float2*)&As[k][ty * 2];
            float4 rb = *(const float4*)&Bs[k][tx * 4];
            acc[0][0] += ra.x * rb.x; acc[0][1] += ra.x * rb.y;
            acc[0][2] += ra.x * rb.z; acc[0][3] += ra.x * rb.w;
            acc[1][0] += ra.y * rb.x; acc[1][1] += ra.y * rb.y;
            acc[1][2] += ra.y * rb.z; acc[1][3] += ra.y * rb.w;
        }
        __syncthreads();
    }
#pragma unroll
    for (int i = 0; i < 2; i++)
#pragma unroll
        for (int j = 0; j < 4; j++)
            C[(ty * 2 + i) * ldc + n0 + tx * 4 + j] = acc[i][j];
}

// -------------------- encoder step: gh partials --------------------
__global__ __launch_bounds__(256) void enc_gemm(const float* __restrict__ Wf,
                                                const float* __restrict__ Wb) {
    int dir = blockIdx.z, ks = blockIdx.y;
    const float* A = (dir ? g_hb : g_hf) + ks * 256;
    const float* W = (dir ? Wb : Wf) + ks * 256;
    float* C = g_epart + (dir * 2 + ks) * (B_ * H3_);
    gemm32_tile<16>(A, H_, W, H_, C, H3_, blockIdx.x * 64);
}

__global__ void enc_pointwise(const int* __restrict__ slen,
                              const float* __restrict__ bhh_f,
                              const float* __restrict__ bhh_b, int t) {
    int idx = blockIdx.x * 256 + threadIdx.x;   // < 32*512
    int dir = blockIdx.y;
    int b = idx >> 9, j = idx & 511;
    int tf = dir ? (S_ - 1 - t) : t;
    const float* gx = (dir ? g_gx_b : g_gx_f) + (b * S_ + tf) * H3_;
    const float* p0 = g_epart + (dir * 2 + 0) * (B_ * H3_) + b * H3_;
    const float* p1 = g_epart + (dir * 2 + 1) * (B_ * H3_) + b * H3_;
    const float* bhh = dir ? bhh_b : bhh_f;
    float* hst = dir ? g_hb : g_hf;
    float ghr = p0[j] + p1[j] + bhh[j];
    float ghz = p0[H_ + j] + p1[H_ + j] + bhh[H_ + j];
    float ghn = p0[2 * H_ + j] + p1[2 * H_ + j] + bhh[2 * H_ + j];
    float h = hst[idx];
    float r = sigf(gx[j] + ghr);
    float z = sigf(gx[H_ + j] + ghz);
    float n = tanhf(gx[2 * H_ + j] + r * ghn);
    float hn = (1.f - z) * n + z * h;
    bool m = tf < slen[b];
    hst[idx] = m ? hn : h;
    g_srchid[(b * S_ + tf) * 1024 + dir * H_ + j] = m ? hn : 0.f;
}

// -------------------- decoder: a = hd @ A_W^T (partials) --------------------
__global__ __launch_bounds__(256) void a_gemm(const float* __restrict__ AW) {
    int ks = blockIdx.y;
    const float* A = g_hd + ks * 256;
    const float* W = AW + ks * 256;
    float* C = g_apart + ks * (B_ * H_);
    gemm32_tile<16>(A, H_, W, H_, C, H_, blockIdx.x * 64);
}

// -------------------- fused attention: energies + softmax + context + x --------------------
__global__ __launch_bounds__(256) void attn_fused(const float* __restrict__ Ab,
                                                  const float* __restrict__ Av,
                                                  const int* __restrict__ slen,
                                                  const int* __restrict__ tseq,
                                                  const float* __restrict__ temb, int t) {
    int b = blockIdx.x;
    int tid = threadIdx.x, lane = tid & 31, w = tid >> 5;
    __shared__ float a_sm[H_];
    __shared__ float wts[S_];

    for (int j = tid; j < H_; j += 256)
        a_sm[j] = g_apart[b * H_ + j] + g_apart[B_ * H_ + b * H_ + j] + Ab[j];
    __syncthreads();

    int L = slen[b];
#pragma unroll
    for (int si = 0; si < 8; si++) {
        int s = w * 8 + si;
        const float* u = g_Uh + (b * S_ + s) * H_;
        float p = 0.f;
#pragma unroll 4
        for (int j = lane; j < H_; j += 32)
            p += Av[j] * tanhf(u[j] + a_sm[j]);
#pragma unroll
        for (int o = 16; o > 0; o >>= 1) p += __shfl_xor_sync(0xffffffffu, p, o);
        if (lane == 0) wts[s] = (s < L) ? p : p - 1e9f;
    }
    __syncthreads();

    if (w == 0) {
        float e0 = wts[lane], e1 = wts[lane + 32];
        float m = fmaxf(e0, e1);
#pragma unroll
        for (int o = 16; o > 0; o >>= 1) m = fmaxf(m, __shfl_xor_sync(0xffffffffu, m, o));
        float x0 = __expf(e0 - m), x1 = __expf(e1 - m);
        float sm = x0 + x1;
#pragma unroll
        for (int o = 16; o > 0; o >>= 1) sm += __shfl_xor_sync(0xffffffffu, sm, o);
        float inv = 1.f / sm;
        wts[lane] = x0 * inv;
        wts[lane + 32] = x1 * inv;
    }
    __syncthreads();

    for (int j = tid; j < 1024; j += 256) {
        float c = 0.f;
        const float* sp = g_srchid + b * S_ * 1024 + j;
#pragma unroll 16
        for (int s = 0; s < S_; s++) c += wts[s] * sp[s * 1024];
        g_x[b * H3_ + H_ + j] = c;
    }
    int tok = tseq[b * T_ + t];
    for (int j = tid; j < H_; j += 256)
        g_x[b * H3_ + j] = temb[tok * H_ + j];
}

// -------------------- decoder main gemm: gxd (3 K-chunks) + ghd (1 chunk) --------------------
__global__ __launch_bounds__(256) void dec_gemm(const float* __restrict__ dWih,
                                                const float* __restrict__ dWhh) {
    int y = blockIdx.y;
    const float* A; int lda; const float* W; int ldw;
    if (y < 3) { A = g_x + y * 512; lda = H3_; W = dWih + y * 512; ldw = H3_; }
    else       { A = g_hd;          lda = H_;  W = dWhh;           ldw = H_; }
    float* C = g_dpart + y * (B_ * H3_);
    gemm32_tile<32>(A, lda, W, ldw, C, H3_, blockIdx.x * 64);
}

__global__ void dec_pointwise(const int* __restrict__ tlen,
                              const float* __restrict__ bih,
                              const float* __restrict__ bhh, int t) {
    int idx = blockIdx.x * 256 + threadIdx.x;   // < 32*512
    int b = idx >> 9, j = idx & 511;
    const float* d0 = g_dpart + b * H3_;
    const float* d1 = g_dpart + 1 * (B_ * H3_) + b * H3_;
    const float* d2 = g_dpart + 2 * (B_ * H3_) + b * H3_;
    const float* d3 = g_dpart + 3 * (B_ * H3_) + b * H3_;
    float gxr = d0[j] + d1[j] + d2[j] + bih[j];
    float gxz = d0[H_ + j] + d1[H_ + j] + d2[H_ + j] + bih[H_ + j];
    float gxn = d0[2 * H_ + j] + d1[2 * H_ + j] + d2[2 * H_ + j] + bih[2 * H_ + j];
    float ghr = d3[j] + bhh[j];
    float ghz = d3[H_ + j] + bhh[H_ + j];
    float ghn = d3[2 * H_ + j] + bhh[2 * H_ + j];
    float h = g_hd[idx];
    float r = sigf(gxr + ghr);
    float z = sigf(gxz + ghz);
    float n = tanhf(gxn + r * ghn);
    float hn = (1.f - z) * n + z * h;
    bool m = t < tlen[b];
    g_hd[idx] = m ? hn : h;
    g_decout[(b * T_ + t) * H_ + j] = m ? hn : 0.f;
}

// -------------------- bf16 conversions --------------------
__global__ void conv_W(const float* __restrict__ W) {
    int i = (blockIdx.x * 256 + threadIdx.x) * 4;   // < 32000*512
    float4 v = *(const float4*)&W[i];
    g_Wbf[i] = __float2bfloat16(v.x);
    g_Wbf[i + 1] = __float2bfloat16(v.y);
    g_Wbf[i + 2] = __float2bfloat16(v.z);
    g_Wbf[i + 3] = __float2bfloat16(v.w);
}

__global__ void conv_dec() {
    int i = (blockIdx.x * 256 + threadIdx.x) * 4;   // < 2048*512
    float4 v = *(const float4*)&g_decout[i];
    g_decbf[i] = __float2bfloat16(v.x);
    g_decbf[i + 1] = __float2bfloat16(v.y);
    g_decbf[i + 2] = __float2bfloat16(v.z);
    g_decbf[i + 3] = __float2bfloat16(v.w);
}

// -------------------- bf16 tensor-core logits GEMM + exp-sum + pick --------------------
__device__ __forceinline__ void ldm_x4(uint32_t& r0, uint32_t& r1, uint32_t& r2, uint32_t& r3,
                                       uint32_t addr) {
    asm volatile("ldmatrix.sync.aligned.m8n8.x4.shared.b16 {%0,%1,%2,%3},[%4];\n"
                 : "=r"(r0), "=r"(r1), "=r"(r2), "=r"(r3) : "r"(addr));
}
__device__ __forceinline__ void mma16816(float* d, const uint32_t* a, const uint32_t* b) {
    asm volatile("mma.sync.aligned.m16n8k16.row.col.f32.bf16.bf16.f32 "
                 "{%0,%1,%2,%3},{%4,%5,%6,%7},{%8,%9},{%0,%1,%2,%3};\n"
                 : "+f"(d[0]), "+f"(d[1]), "+f"(d[2]), "+f"(d[3])
                 : "r"(a[0]), "r"(a[1]), "r"(a[2]), "r"(a[3]), "r"(b[0]), "r"(b[1]));
}

__global__ __launch_bounds__(256) void logits_mma(const float* __restrict__ bias,
                                                  const int* __restrict__ tseq) {
    __shared__ __nv_bfloat16 As[128][40];
    __shared__ __nv_bfloat16 Bs[128][40];
    __shared__ float rowsum[128][2];
    int tid = threadIdx.x, lane = tid & 31, wid = tid >> 5;
    int wm = wid & 3, wn = wid >> 2;
    int row0 = blockIdx.y * 128, col0 = blockIdx.x * 128;

    float acc[2][8][4];
#pragma unroll
    for (int mt = 0; mt < 2; mt++)
#pragma unroll
        for (int nt = 0; nt < 8; nt++)
#pragma unroll
            for (int c = 0; c < 4; c++) acc[mt][nt][c] = 0.f;

    for (int k0 = 0; k0 < H_; k0 += 32) {
        {
            int r = tid >> 2, c = tid & 3;
            *(uint4*)&As[r][c * 8] = *(const uint4*)&g_decbf[(row0 + r) * H_ + k0 + c * 8];
            *(uint4*)&As[r + 64][c * 8] = *(const uint4*)&g_decbf[(row0 + r + 64) * H_ + k0 + c * 8];
            *(uint4*)&Bs[r][c * 8] = *(const uint4*)&g_Wbf[(col0 + r) * H_ + k0 + c * 8];
            *(uint4*)&Bs[r + 64][c * 8] = *(const uint4*)&g_Wbf[(col0 + r + 64) * H_ + k0 + c * 8];
        }
        __syncthreads();
#pragma unroll
        for (int kk = 0; kk < 2; kk++) {
            int kb = kk * 16;
            uint32_t af[2][4];
#pragma unroll
            for (int mt = 0; mt < 2; mt++) {
                int rrow = wm * 32 + mt * 16 + (lane & 7) + ((lane & 8) ? 8 : 0);
                int rcol = kb + ((lane & 16) ? 8 : 0);
                uint32_t addr = (uint32_t)__cvta_generic_to_shared(&As[rrow][rcol]);
                ldm_x4(af[mt][0], af[mt][1], af[mt][2], af[mt][3], addr);
            }
            uint32_t bfr[8][2];
#pragma unroll
            for (int np = 0; np < 4; np++) {
                int brow = wn * 64 + np * 16 + (lane & 7) + ((lane & 16) ? 8 : 0);
                int bcol = kb + ((lane & 8) ? 8 : 0);
                uint32_t addr = (uint32_t)__cvta_generic_to_shared(&Bs[brow][bcol]);
                ldm_x4(bfr[np * 2][0], bfr[np * 2][1], bfr[np * 2 + 1][0], bfr[np * 2 + 1][1], addr);
            }
#pragma unroll
            for (int mt = 0; mt < 2; mt++)
#pragma unroll
                for (int nt = 0; nt < 8; nt++)
                    mma16816(acc[mt][nt], af[mt], bfr[nt]);
        }
        __syncthreads();
    }

    // epilogue: bias add, exp-sum per row, pick goal logit
    float sums[2][2] = {{0.f, 0.f}, {0.f, 0.f}};
    int gl[2][2];
#pragma unroll
    for (int mt = 0; mt < 2; mt++)
#pragma unroll
        for (int h = 0; h < 2; h++) {
            int row = row0 + wm * 32 + mt * 16 + (lane >> 2) + h * 8;
            int tt = row & 63;
            gl[mt][h] = (tt < T_ - 1) ? tseq[(row >> 6) * T_ + tt + 1] : 0;
        }
#pragma unroll
    for (int mt = 0; mt < 2; mt++)
#pragma unroll
        for (int nt = 0; nt < 8; nt++) {
            int cbase = col0 + wn * 64 + nt * 8 + (lane & 3) * 2;
            float b0 = bias[cbase], b1 = bias[cbase + 1];
#pragma unroll
            for (int h = 0; h < 2; h++) {
                float v0 = acc[mt][nt][h * 2 + 0] + b0;
                float v1 = acc[mt][nt][h * 2 + 1] + b1;
                sums[mt][h] += __expf(v0) + __expf(v1);
                int row = row0 + wm * 32 + mt * 16 + (lane >> 2) + h * 8;
                if (cbase == gl[mt][h]) g_picked[row] = v0;
                if (cbase + 1 == gl[mt][h]) g_picked[row] = v1;
            }
        }
#pragma unroll
    for (int mt = 0; mt < 2; mt++)
#pragma unroll
        for (int h = 0; h < 2; h++) {
            float s = sums[mt][h];
            s += __shfl_xor_sync(0xffffffffu, s, 1);
            s += __shfl_xor_sync(0xffffffffu, s, 2);
            if ((lane & 3) == 0)
                rowsum[wm * 32 + mt * 16 + (lane >> 2) + h * 8][wn] = s;
        }
    __syncthreads();
    if (tid < 128)
        g_partial[(row0 + tid) * NVT + blockIdx.x] = rowsum[tid][0] + rowsum[tid][1];
}

// -------------------- per-row lse + nll --------------------
__global__ void rowloss_kernel(const int* __restrict__ tseq) {
    int r = blockIdx.x, tid = threadIdx.x;
    float s = 0.f;
    for (int v = tid; v < NVT; v += 128) s += g_partial[r * NVT + v];
#pragma unroll
    for (int o = 16; o > 0; o >>= 1) s += __shfl_xor_sync(0xffffffffu, s, o);
    __shared__ float w[4];
    if ((tid & 31) == 0) w[tid >> 5] = s;
    __syncthreads();
    if (tid == 0) {
        float sum = w[0] + w[1] + w[2] + w[3];
        int b = r >> 6, t = r & 63;
        int g = (t < T_ - 1) ? tseq[b * T_ + t + 1] : 0;
        if (g != 0) { g_rowloss[r] = logf(sum) - g_picked[r]; g_rowvalid[r] = 1.f; }
        else        { g_rowloss[r] = 0.f;                     g_rowvalid[r] = 0.f; }
    }
}

__global__ void final_kernel(float* __restrict__ out) {
    int tid = threadIdx.x;
    float s = 0.f, c = 0.f;
    for (int r = tid; r < ROWS; r += 256) { s += g_rowloss[r]; c += g_rowvalid[r]; }
#pragma unroll
    for (int o = 16; o > 0; o >>= 1) {
        s += __shfl_xor_sync(0xffffffffu, s, o);
        c += __shfl_xor_sync(0xffffffffu, c, o);
    }
    __shared__ float ws[8], wc[8];
    if ((tid & 31) == 0) { ws[tid >> 5] = s; wc[tid >> 5] = c; }
    __syncthreads();
    if (tid == 0) {
        float S = 0.f, C = 0.f;
        for (int i = 0; i < 8; i++) { S += ws[i]; C += wc[i]; }
        out[0] = S / C;
    }
}

// -------------------- launch --------------------
extern "C" void kernel_launch(void* const* d_in, const int* in_sizes, int n_in,
                              void* d_out, int out_size) {
    const int*   src_seqs = (const int*)d_in[0];
    const int*   src_len  = (const int*)d_in[1];
    const int*   tgt_seqs = (const int*)d_in[2];
    const int*   tgt_len  = (const int*)d_in[3];
    const float* src_emb  = (const float*)d_in[4];
    const float* eWih_f   = (const float*)d_in[5];
    const float* eWhh_f   = (const float*)d_in[6];
    const float* ebih_f   = (const float*)d_in[7];
    const float* ebhh_f   = (const float*)d_in[8];
    const float* eWih_b   = (const float*)d_in[9];
    const float* eWhh_b   = (const float*)d_in[10];
    const float* ebih_b   = (const float*)d_in[11];
    const float* ebhh_b   = (const float*)d_in[12];
    const float* tgt_emb  = (const float*)d_in[13];
    const float* dWih     = (const float*)d_in[14];
    const float* dWhh     = (const float*)d_in[15];
    const float* dbih     = (const float*)d_in[16];
    const float* dbhh     = (const float*)d_in[17];
    const float* U_w      = (const float*)d_in[18];
    const float* U_b      = (const float*)d_in[19];
    const float* A_W      = (const float*)d_in[20];
    const float* A_b      = (const float*)d_in[21];
    const float* A_v      = (const float*)d_in[22];
    const float* out_w    = (const float*)d_in[23];
    const float* out_b    = (const float*)d_in[24];

    float *esrc, *gxf, *gxb, *srchid, *uh;
    cudaGetSymbolAddress((void**)&esrc, g_esrc);
    cudaGetSymbolAddress((void**)&gxf, g_gx_f);
    cudaGetSymbolAddress((void**)&gxb, g_gx_b);
    cudaGetSymbolAddress((void**)&srchid, g_srchid);
    cudaGetSymbolAddress((void**)&uh, g_Uh);

    init_states<<<64, 256>>>();
    embed_src<<<4096, 256>>>(src_seqs, src_emb);
    conv_W<<<16000, 256>>>(out_w);   // independent; done early

    // gx precompute for both encoder directions
    gemm_dual<64, 64, 16, 4, 4><<<dim3(24, 32, 2), 256>>>(
        esrc, eWih_f, ebih_f, gxf, H_,
        esrc, eWih_b, ebih_b, gxb, H_, ROWS, H3_);

    // encoder recurrence: 2 launches/step
    for (int t = 0; t < S_; t++) {
        enc_gemm<<<dim3(24, 2, 2), 256>>>(eWhh_f, eWhh_b);
        enc_pointwise<<<dim3(64, 2), 256>>>(src_len, ebhh_f, ebhh_b, t);
    }

    // Uh = src_hidden @ U_w^T + U_b
    gemm_dual<64, 64, 16, 4, 4><<<dim3(8, 32, 1), 256>>>(
        srchid, U_w, U_b, uh, 1024,
        srchid, U_w, U_b, uh, 1024, ROWS, H_);

    // decoder recurrence: 4 launches/step
    for (int t = 0; t < T_; t++) {
        a_gemm<<<dim3(8, 2), 256>>>(A_W);
        attn_fused<<<32, 256>>>(A_b, A_v, src_len, tgt_seqs, tgt_emb, t);
        dec_gemm<<<dim3(24, 4), 256>>>(dWih, dWhh);
        dec_pointwise<<<64, 256>>>(tgt_len, dbih, dbhh, t);
    }

    conv_dec<<<1024, 256>>>();
    logits_mma<<<dim3(NVT, 16), 256>>>(out_b, tgt_seqs);
    rowloss_kernel<<<ROWS, 128>>>(tgt_seqs);
    final_kernel<<<1, 256>>>((float*)d_out);
}

// round 4
// speedup vs baseline: 2.8412x; 1.0582x over previous
#include <cuda_runtime.h>
#include <cuda_bf16.h>
#include <math.h>
#include <stdint.h>

// Problem constants
#define B_ 32
#define S_ 64
#define T_ 64
#define H_ 512
#define H3_ 1536
#define V_ 32000
#define NVT 250          // V_/128 vocab tiles
#define ROWS 2048        // B_*S_ == B_*T_
#define NBLK 96          // persistent grid size

// -------------------- scratch (device globals; no allocation) --------------------
__device__ float g_esrc[ROWS * H_];
__device__ float g_gx_f[ROWS * H3_];
__device__ float g_gx_b[ROWS * H3_];
__device__ float g_srchid[ROWS * 1024];
__device__ float g_Uh[ROWS * H_];
__device__ float g_hf[B_ * H_];
__device__ float g_hb[B_ * H_];
__device__ float g_hd[B_ * H_];
__device__ float g_epart[4 * B_ * H3_];    // [dir*2+ksplit][32][1536]
__device__ float g_apart[2 * B_ * H_];     // [ksplit][32][512]
__device__ float g_dpart[4 * B_ * H3_];    // [chunk][32][1536] (0..2 gxd, 3 ghd)
__device__ float g_x[B_ * H3_];            // [emb(512) | context(1024)]
__device__ __nv_bfloat16 g_decbf[ROWS * H_];
__device__ __nv_bfloat16 g_Wbf[V_ * H_];
__device__ float g_partial[ROWS * NVT];
__device__ float g_picked[ROWS];
__device__ float g_rowloss[ROWS];
__device__ float g_rowvalid[ROWS];
__device__ unsigned g_cnt;
__device__ unsigned g_gen;

__device__ __forceinline__ float sigf(float x) { return 1.f / (1.f + __expf(-x)); }

// -------------------- software grid barrier (all NBLK blocks resident) --------------------
__device__ __forceinline__ void gridbar() {
    __threadfence();
    __syncthreads();
    if (threadIdx.x == 0) {
        unsigned my = atomicAdd(&g_gen, 0u);
        if (atomicAdd(&g_cnt, 1u) == NBLK - 1) {
            atomicExch(&g_cnt, 0u);
            __threadfence();
            atomicExch(&g_gen, my + 1u);
        } else {
            while (atomicAdd(&g_gen, 0u) == my) {}
        }
        __threadfence();
    }
    __syncthreads();
}

// -------------------- init / embed --------------------
__global__ void init_states() {
    int i = blockIdx.x * 256 + threadIdx.x;
    if (i < B_ * H_) { g_hf[i] = 0.f; g_hb[i] = 0.f; g_hd[i] = 0.f; }
    if (i == 0) { g_cnt = 0u; g_gen = 0u; }
}

__global__ void embed_src(const int* __restrict__ src_seqs,
                          const float* __restrict__ src_emb) {
    int i = blockIdx.x * 256 + threadIdx.x;
    int bs = i >> 9, j = i & 511;
    int tok = src_seqs[bs];
    g_esrc[i] = src_emb[tok * H_ + j];
}

// -------------------- big fp32 GEMM (gx precompute, Uh) --------------------
template<int BM, int BN, int BK, int TM, int TN>
__global__ void gemm_dual(const float* __restrict__ A0, const float* __restrict__ B0,
                          const float* __restrict__ bias0, float* __restrict__ C0, int K0,
                          const float* __restrict__ A1, const float* __restrict__ B1,
                          const float* __restrict__ bias1, float* __restrict__ C1, int K1,
                          int M, int N) {
    constexpr int NTHREADS = (BM / TM) * (BN / TN);
    __shared__ float As[BK][BM];
    __shared__ float Bs[BK][BN];
    const float* A; const float* Bw; const float* bias; float* C; int K;
    if (blockIdx.z == 0) { A = A0; Bw = B0; bias = bias0; C = C0; K = K0; }
    else                 { A = A1; Bw = B1; bias = bias1; C = C1; K = K1; }
    int tid = threadIdx.x;
    int tx = tid % (BN / TN);
    int ty = tid / (BN / TN);
    int row0 = blockIdx.y * BM;
    int col0 = blockIdx.x * BN;
    float acc[TM][TN];
#pragma unroll
    for (int i = 0; i < TM; i++)
#pragma unroll
        for (int j = 0; j < TN; j++) acc[i][j] = 0.f;
    for (int k0 = 0; k0 < K; k0 += BK) {
        for (int i = tid; i < BM * BK; i += NTHREADS) {
            int m = i / BK, kk = i % BK;
            As[kk][m] = A[(row0 + m) * K + k0 + kk];
        }
        for (int i = tid; i < BN * BK; i += NTHREADS) {
            int n = i / BK, kk = i % BK;
            Bs[kk][n] = Bw[(col0 + n) * K + k0 + kk];
        }
        __syncthreads();
#pragma unroll
        for (int kk = 0; kk < BK; kk++) {
            float ra[TM], rb[TN];
#pragma unroll
            for (int i = 0; i < TM; i++) ra[i] = As[kk][ty * TM + i];
#pragma unroll
            for (int j = 0; j < TN; j++) rb[j] = Bs[kk][tx * TN + j];
#pragma unroll
            for (int i = 0; i < TM; i++)
#pragma unroll
                for (int j = 0; j < TN; j++) acc[i][j] += ra[i] * rb[j];
        }
        __syncthreads();
    }
#pragma unroll
    for (int i = 0; i < TM; i++)
#pragma unroll
        for (int j = 0; j < TN; j++) {
            int r = row0 + ty * TM + i;
            int c = col0 + tx * TN + j;
            C[r * N + c] = acc[i][j] + bias[c];
        }
}

// -------------------- small M=32 GEMM tile: C[32, n0:n0+64] = A[32,KT*16] @ W^T --------------------
template<int KTILES>
__device__ __forceinline__ void gemm32_tile(const float* __restrict__ A, int lda,
                                            const float* __restrict__ W, int ldw,
                                            float* __restrict__ C, int ldc, int n0) {
    __shared__ float As[16][34];
    __shared__ float Bs[16][68];
    int tid = threadIdx.x;
    int tx = tid & 15;          // n/4
    int ty = tid >> 4;          // m/2
    float acc[2][4];
#pragma unroll
    for (int i = 0; i < 2; i++)
#pragma unroll
        for (int j = 0; j < 4; j++) acc[i][j] = 0.f;

    for (int kt = 0; kt < KTILES; kt++) {
        int kb = kt * 16;
        {
            int k = tid & 15, m = tid >> 4;
            As[k][m] = A[m * lda + kb + k];
            As[k][m + 16] = A[(m + 16) * lda + kb + k];
        }
        {
#pragma unroll
            for (int r = 0; r < 4; r++) {
                int i = tid + r * 256;
                int k = i & 15, n = i >> 4;
                Bs[k][n] = W[(n0 + n) * ldw + kb + k];
            }
        }
        __syncthreads();
#pragma unroll
        for (int k = 0; k < 16; k++) {
            float2 ra = *(const float2*)&As[k][ty * 2];
            float4 rb = *(const float4*)&Bs[k][tx * 4];
            acc[0][0] += ra.x * rb.x; acc[0][1] += ra.x * rb.y;
            acc[0][2] += ra.x * rb.z; acc[0][3] += ra.x * rb.w;
            acc[1][0] += ra.y * rb.x; acc[1][1] += ra.y * rb.y;
            acc[1][2] += ra.y * rb.z; acc[1][3] += ra.y * rb.w;
        }
        __syncthreads();
    }
#pragma unroll
    for (int i = 0; i < 2; i++)
#pragma unroll
        for (int j = 0; j < 4; j++)
            C[(ty * 2 + i) * ldc + n0 + tx * 4 + j] = acc[i][j];
}

// -------------------- persistent encoder: 64 steps, 2 barriers/step --------------------
__global__ __launch_bounds__(256) void enc_persist(const float* __restrict__ Wf,
                                                   const float* __restrict__ Wb,
                                                   const float* __restrict__ bhh_f,
                                                   const float* __restrict__ bhh_b,
                                                   const int* __restrict__ slen) {
    int bid = blockIdx.x;
    int tid = threadIdx.x;
    // work decomposition for stage A: dir(2) x ksplit(2) x ntile(24) == 96
    int dir = bid / 48;
    int rr = bid % 48;
    int ks = rr / 24;
    int nt = rr % 24;
    const float* Astate = (dir ? g_hb : g_hf) + ks * 256;
    const float* W = (dir ? Wb : Wf) + ks * 256;
    float* C = g_epart + (dir * 2 + ks) * (B_ * H3_);

    for (int t = 0; t < S_; t++) {
        // stage A: gh partial gemm (one 32x64 tile per block)
        gemm32_tile<16>(Astate, H_, W, H_, C, H3_, nt * 64);
        gridbar();
        // stage B: pointwise over 2*32*512 elements
        for (int i = bid * 256 + tid; i < 2 * B_ * H_; i += NBLK * 256) {
            int d = i >> 14;            // dir
            int idx = i & 16383;
            int b = idx >> 9, j = idx & 511;
            int tf = d ? (S_ - 1 - t) : t;
            const float* gx = (d ? g_gx_b : g_gx_f) + (b * S_ + tf) * H3_;
            const float* p0 = g_epart + (d * 2 + 0) * (B_ * H3_) + b * H3_;
            const float* p1 = g_epart + (d * 2 + 1) * (B_ * H3_) + b * H3_;
            const float* bhh = d ? bhh_b : bhh_f;
            float* hst = d ? g_hb : g_hf;
            float ghr = p0[j] + p1[j] + bhh[j];
            float ghz = p0[H_ + j] + p1[H_ + j] + bhh[H_ + j];
            float ghn = p0[2 * H_ + j] + p1[2 * H_ + j] + bhh[2 * H_ + j];
            float h = hst[idx];
            float r = sigf(gx[j] + ghr);
            float z = sigf(gx[H_ + j] + ghz);
            float n = tanhf(gx[2 * H_ + j] + r * ghn);
            float hn = (1.f - z) * n + z * h;
            bool m = tf < slen[b];
            hst[idx] = m ? hn : h;
            g_srchid[(b * S_ + tf) * 1024 + d * H_ + j] = m ? hn : 0.f;
        }
        gridbar();
    }
}

// -------------------- persistent decoder: 64 steps, 4 barriers/step --------------------
__global__ __launch_bounds__(256) void dec_persist(const float* __restrict__ AW,
                                                   const float* __restrict__ Ab,
                                                   const float* __restrict__ Av,
                                                   const float* __restrict__ dWih,
                                                   const float* __restrict__ dWhh,
                                                   const float* __restrict__ dbih,
                                                   const float* __restrict__ dbhh,
                                                   const int* __restrict__ slen,
                                                   const int* __restrict__ tlen,
                                                   const int* __restrict__ tseq,
                                                   const float* __restrict__ temb) {
    int bid = blockIdx.x;
    int tid = threadIdx.x, lane = tid & 31, w = tid >> 5;
    __shared__ float a_sm[H_];
    __shared__ float wts[S_];

    for (int t = 0; t < T_; t++) {
        // ---- stage A: a = hd @ A_W^T partials (16 tiles) + embedding fill (80 blocks) ----
        if (bid < 16) {
            int ks = bid / 8, nt = bid % 8;
            gemm32_tile<16>(g_hd + ks * 256, H_, AW + ks * 256, H_,
                            g_apart + ks * (B_ * H_), H_, nt * 64);
        } else {
            int i = (bid - 16) * 256 + tid;   // < 80*256, covers 16384
            if (i < B_ * H_) {
                int b = i >> 9, j = i & 511;
                int tok = tseq[b * T_ + t];
                g_x[b * H3_ + j] = temb[tok * H_ + j];
            }
        }
        gridbar();

        // ---- stage B: fused attention for bid<32 (one batch per block) ----
        if (bid < B_) {
            int b = bid;
            for (int j = tid; j < H_; j += 256)
                a_sm[j] = g_apart[b * H_ + j] + g_apart[B_ * H_ + b * H_ + j] + Ab[j];
            __syncthreads();
            int L = slen[b];
#pragma unroll
            for (int si = 0; si < 8; si++) {
                int s = w * 8 + si;
                const float* u = g_Uh + (b * S_ + s) * H_;
                float p = 0.f;
#pragma unroll 4
                for (int j = lane; j < H_; j += 32)
                    p += Av[j] * tanhf(u[j] + a_sm[j]);
#pragma unroll
                for (int o = 16; o > 0; o >>= 1) p += __shfl_xor_sync(0xffffffffu, p, o);
                if (lane == 0) wts[s] = (s < L) ? p : p - 1e9f;
            }
            __syncthreads();
            if (w == 0) {
                float e0 = wts[lane], e1 = wts[lane + 32];
                float m = fmaxf(e0, e1);
#pragma unroll
                for (int o = 16; o > 0; o >>= 1) m = fmaxf(m, __shfl_xor_sync(0xffffffffu, m, o));
                float x0 = __expf(e0 - m), x1 = __expf(e1 - m);
                float sm = x0 + x1;
#pragma unroll
                for (int o = 16; o > 0; o >>= 1) sm += __shfl_xor_sync(0xffffffffu, sm, o);
                float inv = 1.f / sm;
                wts[lane] = x0 * inv;
                wts[lane + 32] = x1 * inv;
            }
            __syncthreads();
            for (int j = tid; j < 1024; j += 256) {
                float c = 0.f;
                const float* sp = g_srchid + b * S_ * 1024 + j;
#pragma unroll 16
                for (int s = 0; s < S_; s++) c += wts[s] * sp[s * 1024];
                g_x[b * H3_ + H_ + j] = c;
            }
        }
        gridbar();

        // ---- stage C: main decoder gemm, 96 tiles: y(4 chunks) x ntile(24) ----
        {
            int y = bid / 24, nt = bid % 24;
            const float* A; int lda; const float* W; int ldw;
            if (y < 3) { A = g_x + y * 512; lda = H3_; W = dWih + y * 512; ldw = H3_; }
            else       { A = g_hd;          lda = H_;  W = dWhh;           ldw = H_; }
            gemm32_tile<32>(A, lda, W, ldw, g_dpart + y * (B_ * H3_), H3_, nt * 64);
        }
        gridbar();

        // ---- stage D: pointwise + bf16 decout ----
        {
            int i = bid * 256 + tid;     // 24576 >= 16384: single pass
            if (i < B_ * H_) {
                int b = i >> 9, j = i & 511;
                const float* d0 = g_dpart + b * H3_;
                const float* d1 = g_dpart + 1 * (B_ * H3_) + b * H3_;
                const float* d2 = g_dpart + 2 * (B_ * H3_) + b * H3_;
                const float* d3 = g_dpart + 3 * (B_ * H3_) + b * H3_;
                float gxr = d0[j] + d1[j] + d2[j] + dbih[j];
                float gxz = d0[H_ + j] + d1[H_ + j] + d2[H_ + j] + dbih[H_ + j];
                float gxn = d0[2 * H_ + j] + d1[2 * H_ + j] + d2[2 * H_ + j] + dbih[2 * H_ + j];
                float ghr = d3[j] + dbhh[j];
                float ghz = d3[H_ + j] + dbhh[H_ + j];
                float ghn = d3[2 * H_ + j] + dbhh[2 * H_ + j];
                float h = g_hd[i];
                float r = sigf(gxr + ghr);
                float z = sigf(gxz + ghz);
                float n = tanhf(gxn + r * ghn);
                float hn = (1.f - z) * n + z * h;
                bool m = t < tlen[b];
                g_hd[i] = m ? hn : h;
                g_decbf[(b * T_ + t) * H_ + j] = __float2bfloat16(m ? hn : 0.f);
            }
        }
        gridbar();
    }
}

// -------------------- bf16 weight conversion --------------------
__global__ void conv_W(const float* __restrict__ W) {
    int i = (blockIdx.x * 256 + threadIdx.x) * 4;
    float4 v = *(const float4*)&W[i];
    g_Wbf[i] = __float2bfloat16(v.x);
    g_Wbf[i + 1] = __float2bfloat16(v.y);
    g_Wbf[i + 2] = __float2bfloat16(v.z);
    g_Wbf[i + 3] = __float2bfloat16(v.w);
}

// -------------------- bf16 tensor-core logits GEMM + exp-sum + pick --------------------
__device__ __forceinline__ void ldm_x4(uint32_t& r0, uint32_t& r1, uint32_t& r2, uint32_t& r3,
                                       uint32_t addr) {
    asm volatile("ldmatrix.sync.aligned.m8n8.x4.shared.b16 {%0,%1,%2,%3},[%4];\n"
                 : "=r"(r0), "=r"(r1), "=r"(r2), "=r"(r3) : "r"(addr));
}
__device__ __forceinline__ void mma16816(float* d, const uint32_t* a, const uint32_t* b) {
    asm volatile("mma.sync.aligned.m16n8k16.row.col.f32.bf16.bf16.f32 "
                 "{%0,%1,%2,%3},{%4,%5,%6,%7},{%8,%9},{%0,%1,%2,%3};\n"
                 : "+f"(d[0]), "+f"(d[1]), "+f"(d[2]), "+f"(d[3])
                 : "r"(a[0]), "r"(a[1]), "r"(a[2]), "r"(a[3]), "r"(b[0]), "r"(b[1]));
}

__global__ __launch_bounds__(256) void logits_mma(const float* __restrict__ bias,
                                                  const int* __restrict__ tseq) {
    __shared__ __nv_bfloat16 As[128][40];
    __shared__ __nv_bfloat16 Bs[128][40];
    __shared__ float rowsum[128][2];
    int tid = threadIdx.x, lane = tid & 31, wid = tid >> 5;
    int wm = wid & 3, wn = wid >> 2;
    int row0 = blockIdx.y * 128, col0 = blockIdx.x * 128;

    float acc[2][8][4];
#pragma unroll
    for (int mt = 0; mt < 2; mt++)
#pragma unroll
        for (int nt = 0; nt < 8; nt++)
#pragma unroll
            for (int c = 0; c < 4; c++) acc[mt][nt][c] = 0.f;

    for (int k0 = 0; k0 < H_; k0 += 32) {
        {
            int r = tid >> 2, c = tid & 3;
            *(uint4*)&As[r][c * 8] = *(const uint4*)&g_decbf[(row0 + r) * H_ + k0 + c * 8];
            *(uint4*)&As[r + 64][c * 8] = *(const uint4*)&g_decbf[(row0 + r + 64) * H_ + k0 + c * 8];
            *(uint4*)&Bs[r][c * 8] = *(const uint4*)&g_Wbf[(col0 + r) * H_ + k0 + c * 8];
            *(uint4*)&Bs[r + 64][c * 8] = *(const uint4*)&g_Wbf[(col0 + r + 64) * H_ + k0 + c * 8];
        }
        __syncthreads();
#pragma unroll
        for (int kk = 0; kk < 2; kk++) {
            int kb = kk * 16;
            uint32_t af[2][4];
#pragma unroll
            for (int mt = 0; mt < 2; mt++) {
                int rrow = wm * 32 + mt * 16 + (lane & 7) + ((lane & 8) ? 8 : 0);
                int rcol = kb + ((lane & 16) ? 8 : 0);
                uint32_t addr = (uint32_t)__cvta_generic_to_shared(&As[rrow][rcol]);
                ldm_x4(af[mt][0], af[mt][1], af[mt][2], af[mt][3], addr);
            }
            uint32_t bfr[8][2];
#pragma unroll
            for (int np = 0; np < 4; np++) {
                int brow = wn * 64 + np * 16 + (lane & 7) + ((lane & 16) ? 8 : 0);
                int bcol = kb + ((lane & 8) ? 8 : 0);
                uint32_t addr = (uint32_t)__cvta_generic_to_shared(&Bs[brow][bcol]);
                ldm_x4(bfr[np * 2][0], bfr[np * 2][1], bfr[np * 2 + 1][0], bfr[np * 2 + 1][1], addr);
            }
#pragma unroll
            for (int mt = 0; mt < 2; mt++)
#pragma unroll
                for (int nt = 0; nt < 8; nt++)
                    mma16816(acc[mt][nt], af[mt], bfr[nt]);
        }
        __syncthreads();
    }

    float sums[2][2] = {{0.f, 0.f}, {0.f, 0.f}};
    int gl[2][2];
#pragma unroll
    for (int mt = 0; mt < 2; mt++)
#pragma unroll
        for (int h = 0; h < 2; h++) {
            int row = row0 + wm * 32 + mt * 16 + (lane >> 2) + h * 8;
            int tt = row & 63;
            gl[mt][h] = (tt < T_ - 1) ? tseq[(row >> 6) * T_ + tt + 1] : 0;
        }
#pragma unroll
    for (int mt = 0; mt < 2; mt++)
#pragma unroll
        for (int nt = 0; nt < 8; nt++) {
            int cbase = col0 + wn * 64 + nt * 8 + (lane & 3) * 2;
            float b0 = bias[cbase], b1 = bias[cbase + 1];
#pragma unroll
            for (int h = 0; h < 2; h++) {
                float v0 = acc[mt][nt][h * 2 + 0] + b0;
                float v1 = acc[mt][nt][h * 2 + 1] + b1;
                sums[mt][h] += __expf(v0) + __expf(v1);
                int row = row0 + wm * 32 + mt * 16 + (lane >> 2) + h * 8;
                if (cbase == gl[mt][h]) g_picked[row] = v0;
                if (cbase + 1 == gl[mt][h]) g_picked[row] = v1;
            }
        }
#pragma unroll
    for (int mt = 0; mt < 2; mt++)
#pragma unroll
        for (int h = 0; h < 2; h++) {
            float s = sums[mt][h];
            s += __shfl_xor_sync(0xffffffffu, s, 1);
            s += __shfl_xor_sync(0xffffffffu, s, 2);
            if ((lane & 3) == 0)
                rowsum[wm * 32 + mt * 16 + (lane >> 2) + h * 8][wn] = s;
        }
    __syncthreads();
    if (tid < 128)
        g_partial[(row0 + tid) * NVT + blockIdx.x] = rowsum[tid][0] + rowsum[tid][1];
}

// -------------------- per-row lse + nll --------------------
__global__ void rowloss_kernel(const int* __restrict__ tseq) {
    int r = blockIdx.x, tid = threadIdx.x;
    float s = 0.f;
    for (int v = tid; v < NVT; v += 128) s += g_partial[r * NVT + v];
#pragma unroll
    for (int o = 16; o > 0; o >>= 1) s += __shfl_xor_sync(0xffffffffu, s, o);
    __shared__ float w[4];
    if ((tid & 31) == 0) w[tid >> 5] = s;
    __syncthreads();
    if (tid == 0) {
        float sum = w[0] + w[1] + w[2] + w[3];
        int b = r >> 6, t = r & 63;
        int g = (t < T_ - 1) ? tseq[b * T_ + t + 1] : 0;
        if (g != 0) { g_rowloss[r] = logf(sum) - g_picked[r]; g_rowvalid[r] = 1.f; }
        else        { g_rowloss[r] = 0.f;                     g_rowvalid[r] = 0.f; }
    }
}

__global__ void final_kernel(float* __restrict__ out) {
    int tid = threadIdx.x;
    float s = 0.f, c = 0.f;
    for (int r = tid; r < ROWS; r += 256) { s += g_rowloss[r]; c += g_rowvalid[r]; }
#pragma unroll
    for (int o = 16; o > 0; o >>= 1) {
        s += __shfl_xor_sync(0xffffffffu, s, o);
        c += __shfl_xor_sync(0xffffffffu, c, o);
    }
    __shared__ float ws[8], wc[8];
    if ((tid & 31) == 0) { ws[tid >> 5] = s; wc[tid >> 5] = c; }
    __syncthreads();
    if (tid == 0) {
        float S = 0.f, C = 0.f;
        for (int i = 0; i < 8; i++) { S += ws[i]; C += wc[i]; }
        out[0] = S / C;
    }
}

// -------------------- launch --------------------
extern "C" void kernel_launch(void* const* d_in, const int* in_sizes, int n_in,
                              void* d_out, int out_size) {
    const int*   src_seqs = (const int*)d_in[0];
    const int*   src_len  = (const int*)d_in[1];
    const int*   tgt_seqs = (const int*)d_in[2];
    const int*   tgt_len  = (const int*)d_in[3];
    const float* src_emb  = (const float*)d_in[4];
    const float* eWih_f   = (const float*)d_in[5];
    const float* eWhh_f   = (const float*)d_in[6];
    const float* ebih_f   = (const float*)d_in[7];
    const float* ebhh_f   = (const float*)d_in[8];
    const float* eWih_b   = (const float*)d_in[9];
    const float* eWhh_b   = (const float*)d_in[10];
    const float* ebih_b   = (const float*)d_in[11];
    const float* ebhh_b   = (const float*)d_in[12];
    const float* tgt_emb  = (const float*)d_in[13];
    const float* dWih     = (const float*)d_in[14];
    const float* dWhh     = (const float*)d_in[15];
    const float* dbih     = (const float*)d_in[16];
    const float* dbhh     = (const float*)d_in[17];
    const float* U_w      = (const float*)d_in[18];
    const float* U_b      = (const float*)d_in[19];
    const float* A_W      = (const float*)d_in[20];
    const float* A_b      = (const float*)d_in[21];
    const float* A_v      = (const float*)d_in[22];
    const float* out_w    = (const float*)d_in[23];
    const float* out_b    = (const float*)d_in[24];

    float *esrc, *gxf, *gxb, *srchid, *uh;
    cudaGetSymbolAddress((void**)&esrc, g_esrc);
    cudaGetSymbolAddress((void**)&gxf, g_gx_f);
    cudaGetSymbolAddress((void**)&gxb, g_gx_b);
    cudaGetSymbolAddress((void**)&srchid, g_srchid);
    cudaGetSymbolAddress((void**)&uh, g_Uh);

    init_states<<<64, 256>>>();
    embed_src<<<4096, 256>>>(src_seqs, src_emb);
    conv_W<<<16000, 256>>>(out_w);

    // gx precompute for both encoder directions
    gemm_dual<64, 64, 16, 4, 4><<<dim3(24, 32, 2), 256>>>(
        esrc, eWih_f, ebih_f, gxf, H_,
        esrc, eWih_b, ebih_b, gxb, H_, ROWS, H3_);

    // persistent encoder recurrence (1 launch)
    enc_persist<<<NBLK, 256>>>(eWhh_f, eWhh_b, ebhh_f, ebhh_b, src_len);

    // Uh = src_hidden @ U_w^T + U_b
    gemm_dual<64, 64, 16, 4, 4><<<dim3(8, 32, 1), 256>>>(
        srchid, U_w, U_b, uh, 1024,
        srchid, U_w, U_b, uh, 1024, ROWS, H_);

    // persistent decoder recurrence (1 launch)
    dec_persist<<<NBLK, 256>>>(A_W, A_b, A_v, dWih, dWhh, dbih, dbhh,
                               src_len, tgt_len, tgt_seqs, tgt_emb);

    logits_mma<<<dim3(NVT, 16), 256>>>(out_b, tgt_seqs);
    rowloss_kernel<<<ROWS, 128>>>(tgt_seqs);
    final_kernel<<<1, 256>>>((float*)d_out);
}

// round 5
// speedup vs baseline: 2.9254x; 1.0296x over previous
#include <cuda_runtime.h>
#include <cuda_bf16.h>
#include <math.h>
#include <stdint.h>

// Problem constants
#define B_ 32
#define S_ 64
#define T_ 64
#define H_ 512
#define H3_ 1536
#define V_ 32000
#define NVT 250          // V_/128 vocab tiles
#define ROWS 2048        // B_*S_ == B_*T_
#define NBLK 96          // persistent grid size

// -------------------- scratch (device globals; no allocation) --------------------
__device__ float g_esrc[ROWS * H_];
__device__ float g_gx_f[ROWS * H3_];
__device__ float g_gx_b[ROWS * H3_];
__device__ float g_srchid[ROWS * 1024];
__device__ float g_Uh[ROWS * H_];
__device__ float g_hf[B_ * H_];
__device__ float g_hb[B_ * H_];
__device__ float g_hd[B_ * H_];
__device__ float g_epart[4 * B_ * H3_];    // [dir*2+ksplit][32][1536]
__device__ float g_apart[2 * B_ * H_];     // [ksplit][32][512]
__device__ float g_dpart[4 * B_ * H3_];    // [chunk][32][1536] (0..2 gxd, 3 ghd)
__device__ float g_x[B_ * H3_];            // [emb(512) | context(1024)]
__device__ __nv_bfloat16 g_decbf[ROWS * H_];
__device__ __nv_bfloat16 g_Wbf[V_ * H_];
__device__ float g_partial[ROWS * NVT];
__device__ float g_picked[ROWS];
__device__ float g_rowloss[ROWS];
__device__ float g_rowvalid[ROWS];
__device__ unsigned g_cnt;
__device__ unsigned g_gen;

__device__ __forceinline__ float sigf(float x) { return 1.f / (1.f + __expf(-x)); }

// -------------------- software grid barrier (all NBLK blocks resident) --------------------
__device__ __forceinline__ void gridbar() {
    __threadfence();
    __syncthreads();
    if (threadIdx.x == 0) {
        unsigned my = atomicAdd(&g_gen, 0u);
        if (atomicAdd(&g_cnt, 1u) == NBLK - 1) {
            atomicExch(&g_cnt, 0u);
            __threadfence();
            atomicExch(&g_gen, my + 1u);
        } else {
            while (atomicAdd(&g_gen, 0u) == my) {}
        }
        __threadfence();
    }
    __syncthreads();
}

// -------------------- init / embed --------------------
__global__ void init_states() {
    int i = blockIdx.x * 256 + threadIdx.x;
    if (i < B_ * H_) { g_hf[i] = 0.f; g_hb[i] = 0.f; g_hd[i] = 0.f; }
    if (i == 0) { g_cnt = 0u; g_gen = 0u; }
}

__global__ void embed_src(const int* __restrict__ src_seqs,
                          const float* __restrict__ src_emb) {
    int i = blockIdx.x * 256 + threadIdx.x;
    int bs = i >> 9, j = i & 511;
    int tok = src_seqs[bs];
    g_esrc[i] = src_emb[tok * H_ + j];
}

// -------------------- big fp32 GEMM (gx precompute, Uh) --------------------
template<int BM, int BN, int BK, int TM, int TN>
__global__ void gemm_dual(const float* __restrict__ A0, const float* __restrict__ B0,
                          const float* __restrict__ bias0, float* __restrict__ C0, int K0,
                          const float* __restrict__ A1, const float* __restrict__ B1,
                          const float* __restrict__ bias1, float* __restrict__ C1, int K1,
                          int M, int N) {
    constexpr int NTHREADS = (BM / TM) * (BN / TN);
    __shared__ float As[BK][BM];
    __shared__ float Bs[BK][BN];
    const float* A; const float* Bw; const float* bias; float* C; int K;
    if (blockIdx.z == 0) { A = A0; Bw = B0; bias = bias0; C = C0; K = K0; }
    else                 { A = A1; Bw = B1; bias = bias1; C = C1; K = K1; }
    int tid = threadIdx.x;
    int tx = tid % (BN / TN);
    int ty = tid / (BN / TN);
    int row0 = blockIdx.y * BM;
    int col0 = blockIdx.x * BN;
    float acc[TM][TN];
#pragma unroll
    for (int i = 0; i < TM; i++)
#pragma unroll
        for (int j = 0; j < TN; j++) acc[i][j] = 0.f;
    for (int k0 = 0; k0 < K; k0 += BK) {
        for (int i = tid; i < BM * BK; i += NTHREADS) {
            int m = i / BK, kk = i % BK;
            As[kk][m] = A[(row0 + m) * K + k0 + kk];
        }
        for (int i = tid; i < BN * BK; i += NTHREADS) {
            int n = i / BK, kk = i % BK;
            Bs[kk][n] = Bw[(col0 + n) * K + k0 + kk];
        }
        __syncthreads();
#pragma unroll
        for (int kk = 0; kk < BK; kk++) {
            float ra[TM], rb[TN];
#pragma unroll
            for (int i = 0; i < TM; i++) ra[i] = As[kk][ty * TM + i];
#pragma unroll
            for (int j = 0; j < TN; j++) rb[j] = Bs[kk][tx * TN + j];
#pragma unroll
            for (int i = 0; i < TM; i++)
#pragma unroll
                for (int j = 0; j < TN; j++) acc[i][j] += ra[i] * rb[j];
        }
        __syncthreads();
    }
#pragma unroll
    for (int i = 0; i < TM; i++)
#pragma unroll
        for (int j = 0; j < TN; j++) {
            int r = row0 + ty * TM + i;
            int c = col0 + tx * TN + j;
            C[r * N + c] = acc[i][j] + bias[c];
        }
}

// -------------------- small M=32 GEMM tile: C[32, n0:n0+64] = A[32,KT*16] @ W^T --------------------
template<int KTILES>
__device__ __forceinline__ void gemm32_tile(const float* __restrict__ A, int lda,
                                            const float* __restrict__ W, int ldw,
                                            float* __restrict__ C, int ldc, int n0) {
    __shared__ float As[16][34];
    __shared__ float Bs[16][68];
    int tid = threadIdx.x;
    int tx = tid & 15;          // n/4
    int ty = tid >> 4;          // m/2
    float acc[2][4];
#pragma unroll
    for (int i = 0; i < 2; i++)
#pragma unroll
        for (int j = 0; j < 4; j++) acc[i][j] = 0.f;

    for (int kt = 0; kt < KTILES; kt++) {
        int kb = kt * 16;
        {
            int k = tid & 15, m = tid >> 4;
            As[k][m] = A[m * lda + kb + k];
            As[k][m + 16] = A[(m + 16) * lda + kb + k];
        }
        {
#pragma unroll
            for (int r = 0; r < 4; r++) {
                int i = tid + r * 256;
                int k = i & 15, n = i >> 4;
                Bs[k][n] = W[(n0 + n) * ldw + kb + k];
            }
        }
        __syncthreads();
#pragma unroll
        for (int k = 0; k < 16; k++) {
            float2 ra = *(const float2*)&As[k][ty * 2];
            float4 rb = *(const float4*)&Bs[k][tx * 4];
            acc[0][0] += ra.x * rb.x; acc[0][1] += ra.x * rb.y;
            acc[0][2] += ra.x * rb.z; acc[0][3] += ra.x * rb.w;
            acc[1][0] += ra.y * rb.x; acc[1][1] += ra.y * rb.y;
            acc[1][2] += ra.y * rb.z; acc[1][3] += ra.y * rb.w;
        }
        __syncthreads();
    }
#pragma unroll
    for (int i = 0; i < 2; i++)
#pragma unroll
        for (int j = 0; j < 4; j++)
            C[(ty * 2 + i) * ldc + n0 + tx * 4 + j] = acc[i][j];
}

// -------------------- persistent encoder: 64 steps, 2 barriers/step --------------------
__global__ __launch_bounds__(256) void enc_persist(const float* __restrict__ Wf,
                                                   const float* __restrict__ Wb,
                                                   const float* __restrict__ bhh_f,
                                                   const float* __restrict__ bhh_b,
                                                   const int* __restrict__ slen) {
    int bid = blockIdx.x;
    int tid = threadIdx.x;
    // work decomposition for stage A: dir(2) x ksplit(2) x ntile(24) == 96
    int dir = bid / 48;
    int rr = bid % 48;
    int ks = rr / 24;
    int nt = rr % 24;
    const float* Astate = (dir ? g_hb : g_hf) + ks * 256;
    const float* W = (dir ? Wb : Wf) + ks * 256;
    float* C = g_epart + (dir * 2 + ks) * (B_ * H3_);

    for (int t = 0; t < S_; t++) {
        // stage A: gh partial gemm (one 32x64 tile per block)
        gemm32_tile<16>(Astate, H_, W, H_, C, H3_, nt * 64);
        gridbar();
        // stage B: pointwise over 2*32*512 elements
        for (int i = bid * 256 + tid; i < 2 * B_ * H_; i += NBLK * 256) {
            int d = i >> 14;            // dir
            int idx = i & 16383;
            int b = idx >> 9, j = idx & 511;
            int tf = d ? (S_ - 1 - t) : t;
            const float* gx = (d ? g_gx_b : g_gx_f) + (b * S_ + tf) * H3_;
            const float* p0 = g_epart + (d * 2 + 0) * (B_ * H3_) + b * H3_;
            const float* p1 = g_epart + (d * 2 + 1) * (B_ * H3_) + b * H3_;
            const float* bhh = d ? bhh_b : bhh_f;
            float* hst = d ? g_hb : g_hf;
            float ghr = p0[j] + p1[j] + bhh[j];
            float ghz = p0[H_ + j] + p1[H_ + j] + bhh[H_ + j];
            float ghn = p0[2 * H_ + j] + p1[2 * H_ + j] + bhh[2 * H_ + j];
            float h = hst[idx];
            float r = sigf(gx[j] + ghr);
            float z = sigf(gx[H_ + j] + ghz);
            float n = tanhf(gx[2 * H_ + j] + r * ghn);
            float hn = (1.f - z) * n + z * h;
            bool m = tf < slen[b];
            hst[idx] = m ? hn : h;
            g_srchid[(b * S_ + tf) * 1024 + d * H_ + j] = m ? hn : 0.f;
        }
        gridbar();
    }
}

// -------------------- persistent decoder: 64 steps, 4 barriers/step --------------------
__global__ __launch_bounds__(256) void dec_persist(const float* __restrict__ AW,
                                                   const float* __restrict__ Ab,
                                                   const float* __restrict__ Av,
                                                   const float* __restrict__ dWih,
                                                   const float* __restrict__ dWhh,
                                                   const float* __restrict__ dbih,
                                                   const float* __restrict__ dbhh,
                                                   const int* __restrict__ slen,
                                                   const int* __restrict__ tlen,
                                                   const int* __restrict__ tseq,
                                                   const float* __restrict__ temb) {
    int bid = blockIdx.x;
    int tid = threadIdx.x, lane = tid & 31, w = tid >> 5;
    __shared__ float a_sm[H_];
    __shared__ float wts[S_];

    for (int t = 0; t < T_; t++) {
        // ---- stage A: a = hd @ A_W^T partials (16 tiles) + embedding fill (80 blocks) ----
        if (bid < 16) {
            int ks = bid / 8, nt = bid % 8;
            gemm32_tile<16>(g_hd + ks * 256, H_, AW + ks * 256, H_,
                            g_apart + ks * (B_ * H_), H_, nt * 64);
        } else {
            int i = (bid - 16) * 256 + tid;   // < 80*256, covers 16384
            if (i < B_ * H_) {
                int b = i >> 9, j = i & 511;
                int tok = tseq[b * T_ + t];
                g_x[b * H3_ + j] = temb[tok * H_ + j];
            }
        }
        gridbar();

        // ---- stage B: fused attention for bid<32 (one batch per block) ----
        if (bid < B_) {
            int b = bid;
            for (int j = tid; j < H_; j += 256)
                a_sm[j] = g_apart[b * H_ + j] + g_apart[B_ * H_ + b * H_ + j] + Ab[j];
            __syncthreads();
            int L = slen[b];
#pragma unroll
            for (int si = 0; si < 8; si++) {
                int s = w * 8 + si;
                const float* u = g_Uh + (b * S_ + s) * H_;
                float p = 0.f;
#pragma unroll 4
                for (int j = lane; j < H_; j += 32)
                    p += Av[j] * tanhf(u[j] + a_sm[j]);
#pragma unroll
                for (int o = 16; o > 0; o >>= 1) p += __shfl_xor_sync(0xffffffffu, p, o);
                if (lane == 0) wts[s] = (s < L) ? p : p - 1e9f;
            }
            __syncthreads();
            if (w == 0) {
                float e0 = wts[lane], e1 = wts[lane + 32];
                float m = fmaxf(e0, e1);
#pragma unroll
                for (int o = 16; o > 0; o >>= 1) m = fmaxf(m, __shfl_xor_sync(0xffffffffu, m, o));
                float x0 = __expf(e0 - m), x1 = __expf(e1 - m);
                float sm = x0 + x1;
#pragma unroll
                for (int o = 16; o > 0; o >>= 1) sm += __shfl_xor_sync(0xffffffffu, sm, o);
                float inv = 1.f / sm;
                wts[lane] = x0 * inv;
                wts[lane + 32] = x1 * inv;
            }
            __syncthreads();
            for (int j = tid; j < 1024; j += 256) {
                float c = 0.f;
                const float* sp = g_srchid + b * S_ * 1024 + j;
#pragma unroll 16
                for (int s = 0; s < S_; s++) c += wts[s] * sp[s * 1024];
                g_x[b * H3_ + H_ + j] = c;
            }
        }
        gridbar();

        // ---- stage C: main decoder gemm, 96 tiles: y(4 chunks) x ntile(24) ----
        {
            int y = bid / 24, nt = bid % 24;
            const float* A; int lda; const float* W; int ldw;
            if (y < 3) { A = g_x + y * 512; lda = H3_; W = dWih + y * 512; ldw = H3_; }
            else       { A = g_hd;          lda = H_;  W = dWhh;           ldw = H_; }
            gemm32_tile<32>(A, lda, W, ldw, g_dpart + y * (B_ * H3_), H3_, nt * 64);
        }
        gridbar();

        // ---- stage D: pointwise + bf16 decout ----
        {
            int i = bid * 256 + tid;     // 24576 >= 16384: single pass
            if (i < B_ * H_) {
                int b = i >> 9, j = i & 511;
                const float* d0 = g_dpart + b * H3_;
                const float* d1 = g_dpart + 1 * (B_ * H3_) + b * H3_;
                const float* d2 = g_dpart + 2 * (B_ * H3_) + b * H3_;
                const float* d3 = g_dpart + 3 * (B_ * H3_) + b * H3_;
                float gxr = d0[j] + d1[j] + d2[j] + dbih[j];
                float gxz = d0[H_ + j] + d1[H_ + j] + d2[H_ + j] + dbih[H_ + j];
                float gxn = d0[2 * H_ + j] + d1[2 * H_ + j] + d2[2 * H_ + j] + dbih[2 * H_ + j];
                float ghr = d3[j] + dbhh[j];
                float ghz = d3[H_ + j] + dbhh[H_ + j];
                float ghn = d3[2 * H_ + j] + dbhh[2 * H_ + j];
                float h = g_hd[i];
                float r = sigf(gxr + ghr);
                float z = sigf(gxz + ghz);
                float n = tanhf(gxn + r * ghn);
                float hn = (1.f - z) * n + z * h;
                bool m = t < tlen[b];
                g_hd[i] = m ? hn : h;
                g_decbf[(b * T_ + t) * H_ + j] = __float2bfloat16(m ? hn : 0.f);
            }
        }
        gridbar();
    }
}

// -------------------- bf16 weight conversion --------------------
__global__ void conv_W(const float* __restrict__ W) {
    int i = (blockIdx.x * 256 + threadIdx.x) * 4;
    float4 v = *(const float4*)&W[i];
    g_Wbf[i] = __float2bfloat16(v.x);
    g_Wbf[i + 1] = __float2bfloat16(v.y);
    g_Wbf[i + 2] = __float2bfloat16(v.z);
    g_Wbf[i + 3] = __float2bfloat16(v.w);
}

// -------------------- bf16 tensor-core logits GEMM + exp-sum + pick --------------------
__device__ __forceinline__ void ldm_x4(uint32_t& r0, uint32_t& r1, uint32_t& r2, uint32_t& r3,
                                       uint32_t addr) {
    asm volatile("ldmatrix.sync.aligned.m8n8.x4.shared.b16 {%0,%1,%2,%3},[%4];\n"
                 : "=r"(r0), "=r"(r1), "=r"(r2), "=r"(r3) : "r"(addr));
}
__device__ __forceinline__ void mma16816(float* d, const uint32_t* a, const uint32_t* b) {
    asm volatile("mma.sync.aligned.m16n8k16.row.col.f32.bf16.bf16.f32 "
                 "{%0,%1,%2,%3},{%4,%5,%6,%7},{%8,%9},{%0,%1,%2,%3};\n"
                 : "+f"(d[0]), "+f"(d[1]), "+f"(d[2]), "+f"(d[3])
                 : "r"(a[0]), "r"(a[1]), "r"(a[2]), "r"(a[3]), "r"(b[0]), "r"(b[1]));
}

__global__ __launch_bounds__(256) void logits_mma(const float* __restrict__ bias,
                                                  const int* __restrict__ tseq) {
    __shared__ __nv_bfloat16 As[128][40];
    __shared__ __nv_bfloat16 Bs[128][40];
    __shared__ float rowsum[128][2];
    int tid = threadIdx.x, lane = tid & 31, wid = tid >> 5;
    int wm = wid & 3, wn = wid >> 2;
    int row0 = blockIdx.y * 128, col0 = blockIdx.x * 128;

    float acc[2][8][4];
#pragma unroll
    for (int mt = 0; mt < 2; mt++)
#pragma unroll
        for (int nt = 0; nt < 8; nt++)
#pragma unroll
            for (int c = 0; c < 4; c++) acc[mt][nt][c] = 0.f;

    for (int k0 = 0; k0 < H_; k0 += 32) {
        {
            int r = tid >> 2, c = tid & 3;
            *(uint4*)&As[r][c * 8] = *(const uint4*)&g_decbf[(row0 + r) * H_ + k0 + c * 8];
            *(uint4*)&As[r + 64][c * 8] = *(const uint4*)&g_decbf[(row0 + r + 64) * H_ + k0 + c * 8];
            *(uint4*)&Bs[r][c * 8] = *(const uint4*)&g_Wbf[(col0 + r) * H_ + k0 + c * 8];
            *(uint4*)&Bs[r + 64][c * 8] = *(const uint4*)&g_Wbf[(col0 + r + 64) * H_ + k0 + c * 8];
        }
        __syncthreads();
#pragma unroll
        for (int kk = 0; kk < 2; kk++) {
            int kb = kk * 16;
            uint32_t af[2][4];
#pragma unroll
            for (int mt = 0; mt < 2; mt++) {
                int rrow = wm * 32 + mt * 16 + (lane & 7) + ((lane & 8) ? 8 : 0);
                int rcol = kb + ((lane & 16) ? 8 : 0);
                uint32_t addr = (uint32_t)__cvta_generic_to_shared(&As[rrow][rcol]);
                ldm_x4(af[mt][0], af[mt][1], af[mt][2], af[mt][3], addr);
            }
            uint32_t bfr[8][2];
#pragma unroll
            for (int np = 0; np < 4; np++) {
                int brow = wn * 64 + np * 16 + (lane & 7) + ((lane & 16) ? 8 : 0);
                int bcol = kb + ((lane & 8) ? 8 : 0);
                uint32_t addr = (uint32_t)__cvta_generic_to_shared(&Bs[brow][bcol]);
                ldm_x4(bfr[np * 2][0], bfr[np * 2][1], bfr[np * 2 + 1][0], bfr[np * 2 + 1][1], addr);
            }
#pragma unroll
            for (int mt = 0; mt < 2; mt++)
#pragma unroll
                for (int nt = 0; nt < 8; nt++)
                    mma16816(acc[mt][nt], af[mt], bfr[nt]);
        }
        __syncthreads();
    }

    float sums[2][2] = {{0.f, 0.f}, {0.f, 0.f}};
    int gl[2][2];
#pragma unroll
    for (int mt = 0; mt < 2; mt++)
#pragma unroll
        for (int h = 0; h < 2; h++) {
            int row = row0 + wm * 32 + mt * 16 + (lane >> 2) + h * 8;
            int tt = row & 63;
            gl[mt][h] = (tt < T_ - 1) ? tseq[(row >> 6) * T_ + tt + 1] : 0;
        }
#pragma unroll
    for (int mt = 0; mt < 2; mt++)
#pragma unroll
        for (int nt = 0; nt < 8; nt++) {
            int cbase = col0 + wn * 64 + nt * 8 + (lane & 3) * 2;
            float b0 = bias[cbase], b1 = bias[cbase + 1];
#pragma unroll
            for (int h = 0; h < 2; h++) {
                float v0 = acc[mt][nt][h * 2 + 0] + b0;
                float v1 = acc[mt][nt][h * 2 + 1] + b1;
                sums[mt][h] += __expf(v0) + __expf(v1);
                int row = row0 + wm * 32 + mt * 16 + (lane >> 2) + h * 8;
                if (cbase == gl[mt][h]) g_picked[row] = v0;
                if (cbase + 1 == gl[mt][h]) g_picked[row] = v1;
            }
        }
#pragma unroll
    for (int mt = 0; mt < 2; mt++)
#pragma unroll
        for (int h = 0; h < 2; h++) {
            float s = sums[mt][h];
            s += __shfl_xor_sync(0xffffffffu, s, 1);
            s += __shfl_xor_sync(0xffffffffu, s, 2);
            if ((lane & 3) == 0)
                rowsum[wm * 32 + mt * 16 + (lane >> 2) + h * 8][wn] = s;
        }
    __syncthreads();
    if (tid < 128)
        g_partial[(row0 + tid) * NVT + blockIdx.x] = rowsum[tid][0] + rowsum[tid][1];
}

// -------------------- per-row lse + nll --------------------
__global__ void rowloss_kernel(const int* __restrict__ tseq) {
    int r = blockIdx.x, tid = threadIdx.x;
    float s = 0.f;
    for (int v = tid; v < NVT; v += 128) s += g_partial[r * NVT + v];
#pragma unroll
    for (int o = 16; o > 0; o >>= 1) s += __shfl_xor_sync(0xffffffffu, s, o);
    __shared__ float w[4];
    if ((tid & 31) == 0) w[tid >> 5] = s;
    __syncthreads();
    if (tid == 0) {
        float sum = w[0] + w[1] + w[2] + w[3];
        int b = r >> 6, t = r & 63;
        int g = (t < T_ - 1) ? tseq[b * T_ + t + 1] : 0;
        if (g != 0) { g_rowloss[r] = logf(sum) - g_picked[r]; g_rowvalid[r] = 1.f; }
        else        { g_rowloss[r] = 0.f;                     g_rowvalid[r] = 0.f; }
    }
}

__global__ void final_kernel(float* __restrict__ out) {
    int tid = threadIdx.x;
    float s = 0.f, c = 0.f;
    for (int r = tid; r < ROWS; r += 256) { s += g_rowloss[r]; c += g_rowvalid[r]; }
#pragma unroll
    for (int o = 16; o > 0; o >>= 1) {
        s += __shfl_xor_sync(0xffffffffu, s, o);
        c += __shfl_xor_sync(0xffffffffu, c, o);
    }
    __shared__ float ws[8], wc[8];
    if ((tid & 31) == 0) { ws[tid >> 5] = s; wc[tid >> 5] = c; }
    __syncthreads();
    if (tid == 0) {
        float S = 0.f, C = 0.f;
        for (int i = 0; i < 8; i++) { S += ws[i]; C += wc[i]; }
        out[0] = S / C;
    }
}

// -------------------- launch --------------------
extern "C" void kernel_launch(void* const* d_in, const int* in_sizes, int n_in,
                              void* d_out, int out_size) {
    const int*   src_seqs = (const int*)d_in[0];
    const int*   src_len  = (const int*)d_in[1];
    const int*   tgt_seqs = (const int*)d_in[2];
    const int*   tgt_len  = (const int*)d_in[3];
    const float* src_emb  = (const float*)d_in[4];
    const float* eWih_f   = (const float*)d_in[5];
    const float* eWhh_f   = (const float*)d_in[6];
    const float* ebih_f   = (const float*)d_in[7];
    const float* ebhh_f   = (const float*)d_in[8];
    const float* eWih_b   = (const float*)d_in[9];
    const float* eWhh_b   = (const float*)d_in[10];
    const float* ebih_b   = (const float*)d_in[11];
    const float* ebhh_b   = (const float*)d_in[12];
    const float* tgt_emb  = (const float*)d_in[13];
    const float* dWih     = (const float*)d_in[14];
    const float* dWhh     = (const float*)d_in[15];
    const float* dbih     = (const float*)d_in[16];
    const float* dbhh     = (const float*)d_in[17];
    const float* U_w      = (const float*)d_in[18];
    const float* U_b      = (const float*)d_in[19];
    const float* A_W      = (const float*)d_in[20];
    const float* A_b      = (const float*)d_in[21];
    const float* A_v      = (const float*)d_in[22];
    const float* out_w    = (const float*)d_in[23];
    const float* out_b    = (const float*)d_in[24];

    float *esrc, *gxf, *gxb, *srchid, *uh;
    cudaGetSymbolAddress((void**)&esrc, g_esrc);
    cudaGetSymbolAddress((void**)&gxf, g_gx_f);
    cudaGetSymbolAddress((void**)&gxb, g_gx_b);
    cudaGetSymbolAddress((void**)&srchid, g_srchid);
    cudaGetSymbolAddress((void**)&uh, g_Uh);

    init_states<<<64, 256>>>();
    embed_src<<<4096, 256>>>(src_seqs, src_emb);
    conv_W<<<16000, 256>>>(out_w);

    // gx precompute for both encoder directions
    gemm_dual<64, 64, 16, 4, 4><<<dim3(24, 32, 2), 256>>>(
        esrc, eWih_f, ebih_f, gxf, H_,
        esrc, eWih_b, ebih_b, gxb, H_, ROWS, H3_);

    // persistent encoder recurrence (1 launch)
    enc_persist<<<NBLK, 256>>>(eWhh_f, eWhh_b, ebhh_f, ebhh_b, src_len);

    // Uh = src_hidden @ U_w^T + U_b
    gemm_dual<64, 64, 16, 4, 4><<<dim3(8, 32, 1), 256>>>(
        srchid, U_w, U_b, uh, 1024,
        srchid, U_w, U_b, uh, 1024, ROWS, H_);

    // persistent decoder recurrence (1 launch)
    dec_persist<<<NBLK, 256>>>(A_W, A_b, A_v, dWih, dWhh, dbih, dbhh,
                               src_len, tgt_len, tgt_seqs, tgt_emb);

    logits_mma<<<dim3(NVT, 16), 256>>>(out_b, tgt_seqs);
    rowloss_kernel<<<ROWS, 128>>>(tgt_seqs);
    final_kernel<<<1, 256>>>((float*)d_out);
}

// round 6
// speedup vs baseline: 7.2069x; 2.4636x over previous
#include <cuda_runtime.h>
#include <cuda_bf16.h>
#include <math.h>
#include <stdint.h>

#define B_ 32
#define S_ 64
#define T_ 64
#define H_ 512
#define H3_ 1536
#define V_ 32000
#define NVT 250
#define ROWS 2048

typedef __nv_bfloat16 bf16;

// -------------------- device scratch --------------------
__device__ bf16 g_esrcbf[ROWS * H_];
__device__ float g_gxf[ROWS * H3_];
__device__ float g_gxb[ROWS * H3_];
__device__ bf16 g_srchidbf[ROWS * 1024];
__device__ bf16 g_Uhbf[ROWS * H_];
__device__ float g_henc[2][2][B_ * H_];
__device__ bf16  g_hencbf[2][2][B_ * H_];
__device__ float g_hdec[2][B_ * H_];
__device__ bf16  g_hdecbf[2][B_ * H_];
__device__ float g_a[B_ * H_];
__device__ bf16 g_xembbf[B_ * H_];
__device__ bf16 g_cbf[B_ * 1024];
__device__ bf16 g_decbf[ROWS * H_];
__device__ bf16 g_Wihf_bf[H3_ * H_];
__device__ bf16 g_Wihb_bf[H3_ * H_];
__device__ bf16 g_Whhf_bf[H3_ * H_];
__device__ bf16 g_Whhb_bf[H3_ * H_];
__device__ bf16 g_Uw_bf[H_ * 1024];
__device__ bf16 g_AW_bf[H_ * H_];
__device__ bf16 g_dWih_bf[H3_ * H3_];
__device__ bf16 g_dWhh_bf[H3_ * H_];
__device__ bf16 g_Wbf[V_ * H_];
__device__ float g_partial[ROWS * NVT];
__device__ float g_picked[ROWS];
__device__ float g_rowloss[ROWS];
__device__ float g_rowvalid[ROWS];
__device__ unsigned g_cnt, g_gen;

__device__ __forceinline__ float sigf(float x) { return 1.f / (1.f + __expf(-x)); }

__device__ __forceinline__ void gridbar(int nblk) {
    __threadfence();
    __syncthreads();
    if (threadIdx.x == 0) {
        unsigned my = atomicAdd(&g_gen, 0u);
        if (atomicAdd(&g_cnt, 1u) == (unsigned)(nblk - 1)) {
            atomicExch(&g_cnt, 0u);
            __threadfence();
            atomicExch(&g_gen, my + 1u);
        } else {
            while (atomicAdd(&g_gen, 0u) == my) {}
        }
        __threadfence();
    }
    __syncthreads();
}

__device__ __forceinline__ uint32_t cvsm(const void* p) {
    return (uint32_t)__cvta_generic_to_shared(p);
}
__device__ __forceinline__ void ldm_x4(uint32_t* r, uint32_t a) {
    asm volatile("ldmatrix.sync.aligned.m8n8.x4.shared.b16 {%0,%1,%2,%3},[%4];\n"
                 : "=r"(r[0]), "=r"(r[1]), "=r"(r[2]), "=r"(r[3]) : "r"(a));
}
__device__ __forceinline__ void ldm_x2(uint32_t* r, uint32_t a) {
    asm volatile("ldmatrix.sync.aligned.m8n8.x2.shared.b16 {%0,%1},[%2];\n"
                 : "=r"(r[0]), "=r"(r[1]) : "r"(a));
}
__device__ __forceinline__ void mma16816(float* d, const uint32_t* a, const uint32_t* b) {
    asm volatile("mma.sync.aligned.m16n8k16.row.col.f32.bf16.bf16.f32 "
                 "{%0,%1,%2,%3},{%4,%5,%6,%7},{%8,%9},{%0,%1,%2,%3};\n"
                 : "+f"(d[0]), "+f"(d[1]), "+f"(d[2]), "+f"(d[3])
                 : "r"(a[0]), "r"(a[1]), "r"(a[2]), "r"(a[3]), "r"(b[0]), "r"(b[1]));
}

// -------------------- init / embed / convert --------------------
__global__ void init_states() {
    int i = blockIdx.x * 256 + threadIdx.x;
    if (i < B_ * H_) {
        g_henc[0][0][i] = 0.f; g_henc[1][0][i] = 0.f;
        g_hencbf[0][0][i] = __float2bfloat16(0.f);
        g_hencbf[1][0][i] = __float2bfloat16(0.f);
        g_hdec[0][i] = 0.f;
        g_hdecbf[0][i] = __float2bfloat16(0.f);
    }
    if (i == 0) { g_cnt = 0u; g_gen = 0u; }
}

__global__ void embed_src(const int* __restrict__ seqs, const float* __restrict__ emb) {
    int i = blockIdx.x * 256 + threadIdx.x;
    int bs = i >> 9, j = i & 511;
    g_esrcbf[i] = __float2bfloat16(emb[seqs[bs] * H_ + j]);
}

__global__ void conv_bf(bf16* __restrict__ dst, const float* __restrict__ src) {
    int i = (blockIdx.x * 256 + threadIdx.x) * 4;
    float4 v = *(const float4*)&src[i];
    dst[i] = __float2bfloat16(v.x);
    dst[i + 1] = __float2bfloat16(v.y);
    dst[i + 2] = __float2bfloat16(v.z);
    dst[i + 3] = __float2bfloat16(v.w);
}

// -------------------- bf16 mma GEMM: C[2048,N] = A@W^T + bias --------------------
template<int OUT_BF>
__global__ __launch_bounds__(256) void mma_gemm(const bf16* __restrict__ A,
                                                const bf16* __restrict__ W0,
                                                const bf16* __restrict__ W1,
                                                const float* __restrict__ bias0,
                                                const float* __restrict__ bias1,
                                                float* __restrict__ C0, float* __restrict__ C1,
                                                bf16* __restrict__ Cb, int N, int K) {
    __shared__ bf16 As[128][40];
    __shared__ bf16 Bs[128][40];
    const bf16* W = blockIdx.z ? W1 : W0;
    const float* bias = blockIdx.z ? bias1 : bias0;
    float* C = blockIdx.z ? C1 : C0;
    int tid = threadIdx.x, lane = tid & 31, wid = tid >> 5;
    int wm = wid & 3, wn = wid >> 2;
    int row0 = blockIdx.y * 128, col0 = blockIdx.x * 128;
    float acc[2][8][4];
#pragma unroll
    for (int mt = 0; mt < 2; mt++)
#pragma unroll
        for (int nt = 0; nt < 8; nt++)
#pragma unroll
            for (int c = 0; c < 4; c++) acc[mt][nt][c] = 0.f;

    for (int k0 = 0; k0 < K; k0 += 32) {
        int r = tid >> 2, c = tid & 3;
        *(uint4*)&As[r][c * 8] = *(const uint4*)&A[(row0 + r) * K + k0 + c * 8];
        *(uint4*)&As[r + 64][c * 8] = *(const uint4*)&A[(row0 + r + 64) * K + k0 + c * 8];
        *(uint4*)&Bs[r][c * 8] = *(const uint4*)&W[(col0 + r) * K + k0 + c * 8];
        *(uint4*)&Bs[r + 64][c * 8] = *(const uint4*)&W[(col0 + r + 64) * K + k0 + c * 8];
        __syncthreads();
#pragma unroll
        for (int kk = 0; kk < 2; kk++) {
            int kb = kk * 16;
            uint32_t af[2][4];
#pragma unroll
            for (int mt = 0; mt < 2; mt++)
                ldm_x4(af[mt], cvsm(&As[wm * 32 + mt * 16 + (lane & 15)][kb + ((lane & 16) ? 8 : 0)]));
            uint32_t bfr[8][2];
#pragma unroll
            for (int np = 0; np < 4; np++) {
                uint32_t t4[4];
                ldm_x4(t4, cvsm(&Bs[wn * 64 + np * 16 + (lane & 7) + ((lane & 16) ? 8 : 0)][kb + ((lane & 8) ? 8 : 0)]));
                bfr[np * 2][0] = t4[0]; bfr[np * 2][1] = t4[1];
                bfr[np * 2 + 1][0] = t4[2]; bfr[np * 2 + 1][1] = t4[3];
            }
#pragma unroll
            for (int mt = 0; mt < 2; mt++)
#pragma unroll
                for (int nt = 0; nt < 8; nt++)
                    mma16816(acc[mt][nt], af[mt], bfr[nt]);
        }
        __syncthreads();
    }
#pragma unroll
    for (int mt = 0; mt < 2; mt++)
#pragma unroll
        for (int nt = 0; nt < 8; nt++) {
            int cb = col0 + wn * 64 + nt * 8 + (lane & 3) * 2;
            float b0 = bias[cb], b1 = bias[cb + 1];
#pragma unroll
            for (int h = 0; h < 2; h++) {
                int row = row0 + wm * 32 + mt * 16 + (lane >> 2) + h * 8;
                float v0 = acc[mt][nt][h * 2] + b0;
                float v1 = acc[mt][nt][h * 2 + 1] + b1;
                if (OUT_BF) {
                    Cb[row * N + cb] = __float2bfloat16(v0);
                    Cb[row * N + cb + 1] = __float2bfloat16(v1);
                } else {
                    C[row * N + cb] = v0;
                    C[row * N + cb + 1] = v1;
                }
            }
        }
}

// -------------------- persistent encoder: 128 blocks x 128 thr, 1 barrier/step --------------------
__global__ __launch_bounds__(128) void enc_persist(const float* __restrict__ bhh_f,
                                                   const float* __restrict__ bhh_b,
                                                   const int* __restrict__ slen) {
    extern __shared__ char smem[];
    bf16 (*Wsm)[520] = (bf16(*)[520])smem;                       // 24 rows
    bf16 (*Hsm)[520] = (bf16(*)[520])(smem + 24 * 520 * 2);      // 32 rows
    int bid = blockIdx.x, tid = threadIdx.x, lane = tid & 31, w = tid >> 5;
    int dir = bid >> 6, jt = bid & 63;
    const bf16* Wg = dir ? g_Whhb_bf : g_Whhf_bf;
    const float* bhh = dir ? bhh_b : bhh_f;
    const float* gx = dir ? g_gxb : g_gxf;

    for (int i = tid; i < 24 * 64; i += 128) {
        int r = i >> 6, ch = i & 63;
        int grow = (r >> 3) * 512 + jt * 8 + (r & 7);
        *(uint4*)&Wsm[r][ch * 8] = *(const uint4*)&Wg[grow * 512 + ch * 8];
    }

    for (int t = 0; t < S_; t++) {
        int rd = t & 1, wr = rd ^ 1;
        for (int i = tid; i < 32 * 64; i += 128) {
            int r = i >> 6, ch = i & 63;
            *(uint4*)&Hsm[r][ch * 8] = *(const uint4*)&g_hencbf[dir][rd][r * 512 + ch * 8];
        }
        __syncthreads();
        if (w < 2) {
            float acc[3][4] = {{0.f,0.f,0.f,0.f},{0.f,0.f,0.f,0.f},{0.f,0.f,0.f,0.f}};
#pragma unroll 4
            for (int ks = 0; ks < 32; ks++) {
                uint32_t a4[4];
                ldm_x4(a4, cvsm(&Hsm[16 * w + (lane & 15)][ks * 16 + ((lane & 16) ? 8 : 0)]));
#pragma unroll
                for (int g = 0; g < 3; g++) {
                    uint32_t b2[2];
                    ldm_x2(b2, cvsm(&Wsm[g * 8 + (lane & 7)][ks * 16 + ((lane & 8) ? 8 : 0)]));
                    mma16816(acc[g], a4, b2);
                }
            }
            int tf = dir ? (63 - t) : t;
            int r0 = 16 * w + (lane >> 2);
            int c0 = jt * 8 + (lane & 3) * 2;
#pragma unroll
            for (int hh = 0; hh < 2; hh++) {
                int b = r0 + hh * 8;
                bool m = tf < slen[b];
                int base = (b * 64 + tf) * 1536;
#pragma unroll
                for (int cc = 0; cc < 2; cc++) {
                    int j = c0 + cc;
                    int ai = hh * 2 + cc;
                    float ghr = acc[0][ai] + bhh[j];
                    float ghz = acc[1][ai] + bhh[512 + j];
                    float ghn = acc[2][ai] + bhh[1024 + j];
                    float h = g_henc[dir][rd][b * 512 + j];
                    float r = sigf(gx[base + j] + ghr);
                    float z = sigf(gx[base + 512 + j] + ghz);
                    float n = tanhf(gx[base + 1024 + j] + r * ghn);
                    float hn = (1.f - z) * n + z * h;
                    float hout = m ? hn : h;
                    g_henc[dir][wr][b * 512 + j] = hout;
                    g_hencbf[dir][wr][b * 512 + j] = __float2bfloat16(hout);
                    g_srchidbf[(b * 64 + tf) * 1024 + dir * 512 + j] = __float2bfloat16(m ? hn : 0.f);
                }
            }
        }
        gridbar(128);
    }
}

// -------------------- persistent decoder: 96 blocks x 256 thr, 3 barriers/step --------------------
__global__ __launch_bounds__(256) void dec_persist(const float* __restrict__ Ab,
                                                   const float* __restrict__ Av,
                                                   const float* __restrict__ dbih,
                                                   const float* __restrict__ dbhh,
                                                   const int* __restrict__ slen,
                                                   const int* __restrict__ tlen,
                                                   const int* __restrict__ tseq,
                                                   const float* __restrict__ temb) {
    extern __shared__ char smem[];
    int bid = blockIdx.x, tid = threadIdx.x, lane = tid & 31, w = tid >> 5;

    if (bid < 32) {
        int b = bid;
        bf16 (*Uhc)[520] = (bf16(*)[520])smem;                                  // 64 rows
        bf16 (*SHc)[1048] = (bf16(*)[1048])(smem + 64 * 520 * 2);               // 64 rows
        float* a_sm = (float*)(smem + 64 * 520 * 2 + 64 * 1048 * 2);            // 512
        float* wts = a_sm + 512;                                                // 64
        for (int i = tid; i < 64 * 64; i += 256) {
            int s = i >> 6, ch = i & 63;
            *(uint4*)&Uhc[s][ch * 8] = *(const uint4*)&g_Uhbf[(b * 64 + s) * 512 + ch * 8];
        }
        for (int i = tid; i < 64 * 128; i += 256) {
            int s = i >> 7, ch = i & 127;
            *(uint4*)&SHc[s][ch * 8] = *(const uint4*)&g_srchidbf[(b * 64 + s) * 1024 + ch * 8];
        }
        int L = slen[b];
        for (int t = 0; t < T_; t++) {
            int tok = tseq[b * T_ + t];
            for (int j = tid; j < 512; j += 256)
                g_xembbf[b * 512 + j] = __float2bfloat16(temb[tok * 512 + j]);
            gridbar(96);
            for (int j = tid; j < 512; j += 256) a_sm[j] = g_a[b * 512 + j] + Ab[j];
            __syncthreads();
#pragma unroll
            for (int si = 0; si < 8; si++) {
                int s = w * 8 + si;
                float p = 0.f;
#pragma unroll 4
                for (int j = lane; j < 512; j += 32)
                    p += Av[j] * tanhf(__bfloat162float(Uhc[s][j]) + a_sm[j]);
#pragma unroll
                for (int o = 16; o > 0; o >>= 1) p += __shfl_xor_sync(0xffffffffu, p, o);
                if (lane == 0) wts[s] = (s < L) ? p : p - 1e9f;
            }
            __syncthreads();
            if (w == 0) {
                float e0 = wts[lane], e1 = wts[lane + 32];
                float m = fmaxf(e0, e1);
#pragma unroll
                for (int o = 16; o > 0; o >>= 1) m = fmaxf(m, __shfl_xor_sync(0xffffffffu, m, o));
                float x0 = __expf(e0 - m), x1 = __expf(e1 - m);
                float sm = x0 + x1;
#pragma unroll
                for (int o = 16; o > 0; o >>= 1) sm += __shfl_xor_sync(0xffffffffu, sm, o);
                float inv = 1.f / sm;
                wts[lane] = x0 * inv;
                wts[lane + 32] = x1 * inv;
            }
            __syncthreads();
            for (int j = tid; j < 1024; j += 256) {
                float c = 0.f;
#pragma unroll 16
                for (int s = 0; s < 64; s++) c += wts[s] * __bfloat162float(SHc[s][j]);
                g_cbf[b * 1024 + j] = __float2bfloat16(c);
            }
            gridbar(96);
            gridbar(96);
        }
    } else {
        int gid = bid - 32;
        bf16 (*Wih)[1544] = (bf16(*)[1544])smem;                                       // 24
        bf16 (*Whh)[520] = (bf16(*)[520])(smem + 24 * 1544 * 2);                       // 24
        bf16 (*AWc)[520] = (bf16(*)[520])(smem + 24 * 1544 * 2 + 24 * 520 * 2);        // 8
        bf16 (*Asm)[1048] = (bf16(*)[1048])(smem + 24 * 1544 * 2 + 32 * 520 * 2);      // 32
        for (int i = tid; i < 24 * 192; i += 256) {
            int r = i / 192, ch = i % 192;
            int grow = (r >> 3) * 512 + gid * 8 + (r & 7);
            *(uint4*)&Wih[r][ch * 8] = *(const uint4*)&g_dWih_bf[grow * 1536 + ch * 8];
        }
        for (int i = tid; i < 24 * 64; i += 256) {
            int r = i >> 6, ch = i & 63;
            int grow = (r >> 3) * 512 + gid * 8 + (r & 7);
            *(uint4*)&Whh[r][ch * 8] = *(const uint4*)&g_dWhh_bf[grow * 512 + ch * 8];
        }
        for (int i = tid; i < 8 * 64; i += 256) {
            int r = i >> 6, ch = i & 63;
            *(uint4*)&AWc[r][ch * 8] = *(const uint4*)&g_AW_bf[(gid * 8 + r) * 512 + ch * 8];
        }
        for (int t = 0; t < T_; t++) {
            int rd = t & 1, wr = rd ^ 1;
            float accx[3][4] = {{0.f,0.f,0.f,0.f},{0.f,0.f,0.f,0.f},{0.f,0.f,0.f,0.f}};
            float acch[3][4] = {{0.f,0.f,0.f,0.f},{0.f,0.f,0.f,0.f},{0.f,0.f,0.f,0.f}};
            // stage0: a-gemm + gh-gemm on hd
            for (int i = tid; i < 32 * 64; i += 256) {
                int r = i >> 6, ch = i & 63;
                *(uint4*)&Asm[r][512 + ch * 8] = *(const uint4*)&g_hdecbf[rd][r * 512 + ch * 8];
            }
            __syncthreads();
            if (w < 2) {
                float acca[4] = {0.f, 0.f, 0.f, 0.f};
#pragma unroll 4
                for (int ks = 0; ks < 32; ks++) {
                    uint32_t a4[4];
                    ldm_x4(a4, cvsm(&Asm[16 * w + (lane & 15)][512 + ks * 16 + ((lane & 16) ? 8 : 0)]));
                    uint32_t b2[2];
                    ldm_x2(b2, cvsm(&AWc[(lane & 7)][ks * 16 + ((lane & 8) ? 8 : 0)]));
                    mma16816(acca, a4, b2);
#pragma unroll
                    for (int g = 0; g < 3; g++) {
                        uint32_t bh[2];
                        ldm_x2(bh, cvsm(&Whh[g * 8 + (lane & 7)][ks * 16 + ((lane & 8) ? 8 : 0)]));
                        mma16816(acch[g], a4, bh);
                    }
                }
                int r0 = 16 * w + (lane >> 2);
                int c0 = gid * 8 + (lane & 3) * 2;
                g_a[r0 * 512 + c0] = acca[0];
                g_a[r0 * 512 + c0 + 1] = acca[1];
                g_a[(r0 + 8) * 512 + c0] = acca[2];
                g_a[(r0 + 8) * 512 + c0 + 1] = acca[3];
            }
            gridbar(96);
            // stage1: emb part of gx
            for (int i = tid; i < 32 * 64; i += 256) {
                int r = i >> 6, ch = i & 63;
                *(uint4*)&Asm[r][ch * 8] = *(const uint4*)&g_xembbf[r * 512 + ch * 8];
            }
            __syncthreads();
            if (w < 2) {
#pragma unroll 4
                for (int ks = 0; ks < 32; ks++) {
                    uint32_t a4[4];
                    ldm_x4(a4, cvsm(&Asm[16 * w + (lane & 15)][ks * 16 + ((lane & 16) ? 8 : 0)]));
#pragma unroll
                    for (int g = 0; g < 3; g++) {
                        uint32_t b2[2];
                        ldm_x2(b2, cvsm(&Wih[g * 8 + (lane & 7)][ks * 16 + ((lane & 8) ? 8 : 0)]));
                        mma16816(accx[g], a4, b2);
                    }
                }
            }
            gridbar(96);
            // stage2: context part of gx + pointwise
            for (int i = tid; i < 32 * 128; i += 256) {
                int r = i >> 7, ch = i & 127;
                *(uint4*)&Asm[r][ch * 8] = *(const uint4*)&g_cbf[r * 1024 + ch * 8];
            }
            __syncthreads();
            if (w < 2) {
#pragma unroll 4
                for (int ks = 0; ks < 64; ks++) {
                    uint32_t a4[4];
                    ldm_x4(a4, cvsm(&Asm[16 * w + (lane & 15)][ks * 16 + ((lane & 16) ? 8 : 0)]));
#pragma unroll
                    for (int g = 0; g < 3; g++) {
                        uint32_t b2[2];
                        ldm_x2(b2, cvsm(&Wih[g * 8 + (lane & 7)][512 + ks * 16 + ((lane & 8) ? 8 : 0)]));
                        mma16816(accx[g], a4, b2);
                    }
                }
                int r0 = 16 * w + (lane >> 2);
                int c0 = gid * 8 + (lane & 3) * 2;
#pragma unroll
                for (int hh = 0; hh < 2; hh++) {
                    int b = r0 + hh * 8;
                    bool m = t < tlen[b];
#pragma unroll
                    for (int cc = 0; cc < 2; cc++) {
                        int j = c0 + cc;
                        int ai = hh * 2 + cc;
                        float gxr = accx[0][ai] + dbih[j];
                        float gxz = accx[1][ai] + dbih[512 + j];
                        float gxn = accx[2][ai] + dbih[1024 + j];
                        float ghr = acch[0][ai] + dbhh[j];
                        float ghz = acch[1][ai] + dbhh[512 + j];
                        float ghn = acch[2][ai] + dbhh[1024 + j];
                        float h = g_hdec[rd][b * 512 + j];
                        float r = sigf(gxr + ghr);
                        float z = sigf(gxz + ghz);
                        float n = tanhf(gxn + r * ghn);
                        float hn = (1.f - z) * n + z * h;
                        float hout = m ? hn : h;
                        g_hdec[wr][b * 512 + j] = hout;
                        g_hdecbf[wr][b * 512 + j] = __float2bfloat16(hout);
                        g_decbf[(b * 64 + t) * 512 + j] = __float2bfloat16(m ? hn : 0.f);
                    }
                }
            }
            gridbar(96);
        }
    }
}

// -------------------- logits GEMM + exp-sum + pick (validated in R2) --------------------
__global__ __launch_bounds__(256) void logits_mma(const float* __restrict__ bias,
                                                  const int* __restrict__ tseq) {
    __shared__ bf16 As[128][40];
    __shared__ bf16 Bs[128][40];
    __shared__ float rowsum[128][2];
    int tid = threadIdx.x, lane = tid & 31, wid = tid >> 5;
    int wm = wid & 3, wn = wid >> 2;
    int row0 = blockIdx.y * 128, col0 = blockIdx.x * 128;
    float acc[2][8][4];
#pragma unroll
    for (int mt = 0; mt < 2; mt++)
#pragma unroll
        for (int nt = 0; nt < 8; nt++)
#pragma unroll
            for (int c = 0; c < 4; c++) acc[mt][nt][c] = 0.f;

    for (int k0 = 0; k0 < H_; k0 += 32) {
        int r = tid >> 2, c = tid & 3;
        *(uint4*)&As[r][c * 8] = *(const uint4*)&g_decbf[(row0 + r) * H_ + k0 + c * 8];
        *(uint4*)&As[r + 64][c * 8] = *(const uint4*)&g_decbf[(row0 + r + 64) * H_ + k0 + c * 8];
        *(uint4*)&Bs[r][c * 8] = *(const uint4*)&g_Wbf[(col0 + r) * H_ + k0 + c * 8];
        *(uint4*)&Bs[r + 64][c * 8] = *(const uint4*)&g_Wbf[(col0 + r + 64) * H_ + k0 + c * 8];
        __syncthreads();
#pragma unroll
        for (int kk = 0; kk < 2; kk++) {
            int kb = kk * 16;
            uint32_t af[2][4];
#pragma unroll
            for (int mt = 0; mt < 2; mt++)
                ldm_x4(af[mt], cvsm(&As[wm * 32 + mt * 16 + (lane & 15)][kb + ((lane & 16) ? 8 : 0)]));
            uint32_t bfr[8][2];
#pragma unroll
            for (int np = 0; np < 4; np++) {
                uint32_t t4[4];
                ldm_x4(t4, cvsm(&Bs[wn * 64 + np * 16 + (lane & 7) + ((lane & 16) ? 8 : 0)][kb + ((lane & 8) ? 8 : 0)]));
                bfr[np * 2][0] = t4[0]; bfr[np * 2][1] = t4[1];
                bfr[np * 2 + 1][0] = t4[2]; bfr[np * 2 + 1][1] = t4[3];
            }
#pragma unroll
            for (int mt = 0; mt < 2; mt++)
#pragma unroll
                for (int nt = 0; nt < 8; nt++)
                    mma16816(acc[mt][nt], af[mt], bfr[nt]);
        }
        __syncthreads();
    }
    float sums[2][2] = {{0.f, 0.f}, {0.f, 0.f}};
    int gl[2][2];
#pragma unroll
    for (int mt = 0; mt < 2; mt++)
#pragma unroll
        for (int h = 0; h < 2; h++) {
            int row = row0 + wm * 32 + mt * 16 + (lane >> 2) + h * 8;
            int tt = row & 63;
            gl[mt][h] = (tt < T_ - 1) ? tseq[(row >> 6) * T_ + tt + 1] : 0;
        }
#pragma unroll
    for (int mt = 0; mt < 2; mt++)
#pragma unroll
        for (int nt = 0; nt < 8; nt++) {
            int cb = col0 + wn * 64 + nt * 8 + (lane & 3) * 2;
            float b0 = bias[cb], b1 = bias[cb + 1];
#pragma unroll
            for (int h = 0; h < 2; h++) {
                float v0 = acc[mt][nt][h * 2] + b0;
                float v1 = acc[mt][nt][h * 2 + 1] + b1;
                sums[mt][h] += __expf(v0) + __expf(v1);
                int row = row0 + wm * 32 + mt * 16 + (lane >> 2) + h * 8;
                if (cb == gl[mt][h]) g_picked[row] = v0;
                if (cb + 1 == gl[mt][h]) g_picked[row] = v1;
            }
        }
#pragma unroll
    for (int mt = 0; mt < 2; mt++)
#pragma unroll
        for (int h = 0; h < 2; h++) {
            float s = sums[mt][h];
            s += __shfl_xor_sync(0xffffffffu, s, 1);
            s += __shfl_xor_sync(0xffffffffu, s, 2);
            if ((lane & 3) == 0)
                rowsum[wm * 32 + mt * 16 + (lane >> 2) + h * 8][wn] = s;
        }
    __syncthreads();
    if (tid < 128)
        g_partial[(row0 + tid) * NVT + blockIdx.x] = rowsum[tid][0] + rowsum[tid][1];
}

__global__ void rowloss_kernel(const int* __restrict__ tseq) {
    int r = blockIdx.x, tid = threadIdx.x;
    float s = 0.f;
    for (int v = tid; v < NVT; v += 128) s += g_partial[r * NVT + v];
#pragma unroll
    for (int o = 16; o > 0; o >>= 1) s += __shfl_xor_sync(0xffffffffu, s, o);
    __shared__ float w[4];
    if ((tid & 31) == 0) w[tid >> 5] = s;
    __syncthreads();
    if (tid == 0) {
        float sum = w[0] + w[1] + w[2] + w[3];
        int b = r >> 6, t = r & 63;
        int g = (t < T_ - 1) ? tseq[b * T_ + t + 1] : 0;
        if (g != 0) { g_rowloss[r] = logf(sum) - g_picked[r]; g_rowvalid[r] = 1.f; }
        else        { g_rowloss[r] = 0.f;                     g_rowvalid[r] = 0.f; }
    }
}

__global__ void final_kernel(float* __restrict__ out) {
    int tid = threadIdx.x;
    float s = 0.f, c = 0.f;
    for (int r = tid; r < ROWS; r += 256) { s += g_rowloss[r]; c += g_rowvalid[r]; }
#pragma unroll
    for (int o = 16; o > 0; o >>= 1) {
        s += __shfl_xor_sync(0xffffffffu, s, o);
        c += __shfl_xor_sync(0xffffffffu, c, o);
    }
    __shared__ float ws[8], wc[8];
    if ((tid & 31) == 0) { ws[tid >> 5] = s; wc[tid >> 5] = c; }
    __syncthreads();
    if (tid == 0) {
        float S = 0.f, C = 0.f;
        for (int i = 0; i < 8; i++) { S += ws[i]; C += wc[i]; }
        out[0] = S / C;
    }
}

// -------------------- launch --------------------
extern "C" void kernel_launch(void* const* d_in, const int* in_sizes, int n_in,
                              void* d_out, int out_size) {
    const int*   src_seqs = (const int*)d_in[0];
    const int*   src_len  = (const int*)d_in[1];
    const int*   tgt_seqs = (const int*)d_in[2];
    const int*   tgt_len  = (const int*)d_in[3];
    const float* src_emb  = (const float*)d_in[4];
    const float* eWih_f   = (const float*)d_in[5];
    const float* eWhh_f   = (const float*)d_in[6];
    const float* ebih_f   = (const float*)d_in[7];
    const float* ebhh_f   = (const float*)d_in[8];
    const float* eWih_b   = (const float*)d_in[9];
    const float* eWhh_b   = (const float*)d_in[10];
    const float* ebih_b   = (const float*)d_in[11];
    const float* ebhh_b   = (const float*)d_in[12];
    const float* tgt_emb  = (const float*)d_in[13];
    const float* dWih     = (const float*)d_in[14];
    const float* dWhh     = (const float*)d_in[15];
    const float* dbih     = (const float*)d_in[16];
    const float* dbhh     = (const float*)d_in[17];
    const float* U_w      = (const float*)d_in[18];
    const float* U_b      = (const float*)d_in[19];
    const float* A_W      = (const float*)d_in[20];
    const float* A_b      = (const float*)d_in[21];
    const float* A_v      = (const float*)d_in[22];
    const float* out_w    = (const float*)d_in[23];
    const float* out_b    = (const float*)d_in[24];

    bf16 *wihf, *wihb, *whhf, *whhb, *uw, *aw, *dwih, *dwhh, *wbf, *esrc, *srchid, *uhbf;
    float *gxf, *gxb;
    cudaGetSymbolAddress((void**)&wihf, g_Wihf_bf);
    cudaGetSymbolAddress((void**)&wihb, g_Wihb_bf);
    cudaGetSymbolAddress((void**)&whhf, g_Whhf_bf);
    cudaGetSymbolAddress((void**)&whhb, g_Whhb_bf);
    cudaGetSymbolAddress((void**)&uw, g_Uw_bf);
    cudaGetSymbolAddress((void**)&aw, g_AW_bf);
    cudaGetSymbolAddress((void**)&dwih, g_dWih_bf);
    cudaGetSymbolAddress((void**)&dwhh, g_dWhh_bf);
    cudaGetSymbolAddress((void**)&wbf, g_Wbf);
    cudaGetSymbolAddress((void**)&esrc, g_esrcbf);
    cudaGetSymbolAddress((void**)&srchid, g_srchidbf);
    cudaGetSymbolAddress((void**)&uhbf, g_Uhbf);
    cudaGetSymbolAddress((void**)&gxf, g_gxf);
    cudaGetSymbolAddress((void**)&gxb, g_gxb);

    static int attr_done = 0;
    cudaFuncSetAttribute(enc_persist, cudaFuncAttributeMaxDynamicSharedMemorySize, 58240);
    cudaFuncSetAttribute(dec_persist, cudaFuncAttributeMaxDynamicSharedMemorySize, 203008);
    (void)attr_done;

    init_states<<<64, 256>>>();
    embed_src<<<4096, 256>>>(src_seqs, src_emb);
    conv_bf<<<768, 256>>>(wihf, eWih_f);
    conv_bf<<<768, 256>>>(wihb, eWih_b);
    conv_bf<<<768, 256>>>(whhf, eWhh_f);
    conv_bf<<<768, 256>>>(whhb, eWhh_b);
    conv_bf<<<512, 256>>>(uw, U_w);
    conv_bf<<<256, 256>>>(aw, A_W);
    conv_bf<<<2304, 256>>>(dwih, dWih);
    conv_bf<<<768, 256>>>(dwhh, dWhh);
    conv_bf<<<16000, 256>>>(wbf, out_w);

    // gx for both encoder directions (fp32 out)
    mma_gemm<0><<<dim3(12, 16, 2), 256>>>(esrc, wihf, wihb, ebih_f, ebih_b,
                                          gxf, gxb, (bf16*)0, H3_, H_);

    enc_persist<<<128, 128, 58240>>>(ebhh_f, ebhh_b, src_len);

    // Uh (bf16 out)
    mma_gemm<1><<<dim3(4, 16, 1), 256>>>(srchid, uw, uw, U_b, U_b,
                                         (float*)0, (float*)0, uhbf, H_, 1024);

    dec_persist<<<96, 256, 203008>>>(A_b, A_v, dbih, dbhh,
                                     src_len, tgt_len, tgt_seqs, tgt_emb);

    logits_mma<<<dim3(NVT, 16), 256>>>(out_b, tgt_seqs);
    rowloss_kernel<<<ROWS, 128>>>(tgt_seqs);
    final_kernel<<<1, 256>>>((float*)d_out);
}